// round 4
// baseline (speedup 1.0000x reference)
#include <cuda_runtime.h>
#include <cstdint>
#include <cstddef>

// ---------------- problem constants ----------------
#define NMAX 50176
#define EMAX 800000
#define HF   256          // H*F
#define CIN  256
#define XDIM 192

// ---------------- device scratch (static, no allocation) ----------------
__device__ float g_xcomb[(size_t)NMAX * 256];
__device__ float g_xl   [(size_t)NMAX * 256];
__device__ float g_xr   [(size_t)NMAX * 256];
__device__ float g_iden [(size_t)NMAX * 256];
__device__ float g_act  [(size_t)NMAX * 256];
__device__ float g_nu   [(size_t)NMAX * 2];
__device__ float g_logits[(size_t)EMAX * 4];
__device__ int   g_deg [NMAX + 1];
__device__ int   g_off [NMAX + 1];
__device__ int   g_fill[NMAX + 1];
__device__ int   g_ceid[EMAX];
__device__ int   g_csrc[EMAX];

// ---------------- helpers ----------------
__device__ __forceinline__ float wredsum(float v) {
    #pragma unroll
    for (int s = 16; s; s >>= 1) v += __shfl_xor_sync(0xffffffffu, v, s);
    return v;
}

// ---------------- K0: zero CSR counters ----------------
__global__ void zero_counts(int n) {
    int i = blockIdx.x * blockDim.x + threadIdx.x;
    if (i <= n) { g_deg[i] = 0; g_fill[i] = 0; }
}

// ---------------- K1: positional encoder + concat (one warp / node) ----------------
__global__ void node_pre(const float* __restrict__ x, const float* __restrict__ kpts,
                         const float* __restrict__ pts3,
                         const float* __restrict__ pe_w1, const float* __restrict__ pe_b1,
                         const float* __restrict__ pe_g1, const float* __restrict__ pe_bn1,
                         const float* __restrict__ pe_w2, const float* __restrict__ pe_b2,
                         const float* __restrict__ pe_g2, const float* __restrict__ pe_bn2,
                         int n)
{
    int node = (blockIdx.x * blockDim.x + threadIdx.x) >> 5;
    int lane = threadIdx.x & 31;
    if (node >= n) return;

    float u = kpts[2 * node]     * (1.0f / 1216.0f);
    float v = kpts[2 * node + 1] * (1.0f / 352.0f);
    float d = pts3[3 * node + 2];
    d = fminf(fmaxf(d, 0.1f), 100.0f);
    if (lane == 0) { g_nu[2 * node] = u; g_nu[2 * node + 1] = v; }

    // layer1: 3 -> 32 (one output per lane)
    float h1 = pe_b1[lane] + pe_w1[lane * 3] * u + pe_w1[lane * 3 + 1] * v + pe_w1[lane * 3 + 2] * d;
    float m  = wredsum(h1) * (1.0f / 32.0f);
    float c  = h1 - m;
    float vr = wredsum(c * c) * (1.0f / 32.0f);
    float y  = c * rsqrtf(vr + 1e-5f) * pe_g1[lane] + pe_bn1[lane];
    y = y / (1.0f + expf(-y));                       // silu

    // layer2: 32 -> 64 (outputs lane, lane+32)
    float o0 = pe_b2[lane], o1 = pe_b2[lane + 32];
    #pragma unroll
    for (int k = 0; k < 32; k++) {
        float hk = __shfl_sync(0xffffffffu, y, k);
        o0 += pe_w2[lane * 32 + k] * hk;
        o1 += pe_w2[(lane + 32) * 32 + k] * hk;
    }
    float m2 = wredsum(o0 + o1) * (1.0f / 64.0f);
    float c0 = o0 - m2, c1 = o1 - m2;
    float v2 = wredsum(c0 * c0 + c1 * c1) * (1.0f / 64.0f);
    float r  = rsqrtf(v2 + 1e-5f);
    float p0 = c0 * r * pe_g2[lane]      + pe_bn2[lane];
    float p1 = c1 * r * pe_g2[lane + 32] + pe_bn2[lane + 32];

    size_t base = (size_t)node * 256;
    g_xcomb[base + 192 + lane] = p0;
    g_xcomb[base + 224 + lane] = p1;
    #pragma unroll
    for (int i = lane; i < XDIM; i += 32)
        g_xcomb[base + i] = x[(size_t)node * XDIM + i];
}

// ---------------- K2: tiled fp32 GEMM  C[M,256] = A[M,256] @ W[256,256]^T + bias ----------------
__global__ __launch_bounds__(256) void gemm256(const float* __restrict__ A,
                                               const float* __restrict__ W,
                                               const float* __restrict__ bias,
                                               float* __restrict__ C, int M)
{
    __shared__ __align__(16) float As[16][64];
    __shared__ __align__(16) float Bs[16][64];
    int tid = threadIdx.x;
    int tx = tid & 15, ty = tid >> 4;
    int m0 = blockIdx.x * 64, f0 = blockIdx.y * 64;
    int lr = tid >> 2;               // 0..63
    int kg = (tid & 3) * 4;

    float acc[4][4] = {};
    const float* Aptr = A + (size_t)(m0 + lr) * 256;
    const float* Wptr = W + (size_t)(f0 + lr) * 256;
    bool aval = (m0 + lr) < M;

    for (int kt = 0; kt < 256; kt += 16) {
        float4 av = aval ? *(const float4*)(Aptr + kt + kg) : make_float4(0.f, 0.f, 0.f, 0.f);
        float4 bv = *(const float4*)(Wptr + kt + kg);
        As[kg + 0][lr] = av.x; As[kg + 1][lr] = av.y; As[kg + 2][lr] = av.z; As[kg + 3][lr] = av.w;
        Bs[kg + 0][lr] = bv.x; Bs[kg + 1][lr] = bv.y; Bs[kg + 2][lr] = bv.z; Bs[kg + 3][lr] = bv.w;
        __syncthreads();
        #pragma unroll
        for (int k = 0; k < 16; k++) {
            float4 a = *(const float4*)&As[k][ty * 4];
            float4 b = *(const float4*)&Bs[k][tx * 4];
            acc[0][0] += a.x * b.x; acc[0][1] += a.x * b.y; acc[0][2] += a.x * b.z; acc[0][3] += a.x * b.w;
            acc[1][0] += a.y * b.x; acc[1][1] += a.y * b.y; acc[1][2] += a.y * b.z; acc[1][3] += a.y * b.w;
            acc[2][0] += a.z * b.x; acc[2][1] += a.z * b.y; acc[2][2] += a.z * b.z; acc[2][3] += a.z * b.w;
            acc[3][0] += a.w * b.x; acc[3][1] += a.w * b.y; acc[3][2] += a.w * b.z; acc[3][3] += a.w * b.w;
        }
        __syncthreads();
    }
    #pragma unroll
    for (int i = 0; i < 4; i++) {
        int row = m0 + ty * 4 + i;
        if (row < M) {
            #pragma unroll
            for (int j = 0; j < 4; j++) {
                int f = f0 + tx * 4 + j;
                C[(size_t)row * 256 + f] = acc[i][j] + bias[f];
            }
        }
    }
}

// ---------------- K3: CSR build ----------------
__global__ void count_deg(const int* __restrict__ ei, int E) {
    int i = blockIdx.x * blockDim.x + threadIdx.x;
    if (i < E) atomicAdd(&g_deg[ei[E + i]], 1);
}

__global__ void scan_offsets(int n) {
    __shared__ int sh[1024];
    __shared__ int carry;
    int t = threadIdx.x;
    if (t == 0) { carry = 0; g_off[0] = 0; }
    __syncthreads();
    for (int base = 0; base < n; base += 1024) {
        int v = (base + t < n) ? g_deg[base + t] : 0;
        sh[t] = v; __syncthreads();
        for (int s = 1; s < 1024; s <<= 1) {
            int add = (t >= s) ? sh[t - s] : 0;
            __syncthreads();
            sh[t] += add;
            __syncthreads();
        }
        if (base + t < n) g_off[base + t + 1] = carry + sh[t];
        __syncthreads();
        if (t == 0) carry += sh[1023];
        __syncthreads();
    }
}

__global__ void fill_csr(const int* __restrict__ ei, int E) {
    int i = blockIdx.x * blockDim.x + threadIdx.x;
    if (i < E) {
        int d = ei[E + i];
        int p = g_off[d] + atomicAdd(&g_fill[d], 1);
        g_ceid[p] = i;
        g_csrc[p] = ei[i];
    }
}

// ---------------- K4: edge attrs + attention logits (one warp / edge) ----------------
__global__ __launch_bounds__(256) void edge_logits(const int* __restrict__ ei,
                                                   const float* __restrict__ ew,
                                                   const float* __restrict__ att,
                                                   float* __restrict__ dout,
                                                   size_t EA_OFF, int E)
{
    int w = (blockIdx.x * blockDim.x + threadIdx.x) >> 5;
    if (w >= E) return;
    int lane = threadIdx.x & 31;
    int src = __ldg(&ei[w]);
    int dst = __ldg(&ei[E + w]);

    float a0 = g_nu[2 * dst]     - g_nu[2 * src];
    float a1 = g_nu[2 * dst + 1] - g_nu[2 * src + 1];
    float a2 = sqrtf(a0 * a0 + a1 * a1);
    if (lane == 0) {
        dout[EA_OFF + (size_t)w * 3]     = a0;
        dout[EA_OFF + (size_t)w * 3 + 1] = a1;
        dout[EA_OFF + (size_t)w * 3 + 2] = a2;
    }

    int f0 = lane * 8;
    const float* xl = &g_xl[(size_t)src * 256 + f0];
    const float* xr = &g_xr[(size_t)dst * 256 + f0];
    float4 l0 = *(const float4*)xl,       l1 = *(const float4*)(xl + 4);
    float4 r0 = *(const float4*)xr,       r1 = *(const float4*)(xr + 4);
    float vals[8] = { l0.x + r0.x, l0.y + r0.y, l0.z + r0.z, l0.w + r0.w,
                      l1.x + r1.x, l1.y + r1.y, l1.z + r1.z, l1.w + r1.w };
    float acc = 0.0f;
    #pragma unroll
    for (int i = 0; i < 8; i++) {
        int f = f0 + i;
        float vv = vals[i] + __ldg(&ew[f * 3]) * a0 + __ldg(&ew[f * 3 + 1]) * a1 + __ldg(&ew[f * 3 + 2]) * a2;
        vv = vv > 0.0f ? vv : 0.2f * vv;         // leaky_relu
        acc += vv * __ldg(&att[f]);
    }
    acc += __shfl_xor_sync(0xffffffffu, acc, 1);
    acc += __shfl_xor_sync(0xffffffffu, acc, 2);
    acc += __shfl_xor_sync(0xffffffffu, acc, 4);
    if ((lane & 7) == 0) g_logits[(size_t)w * 4 + (lane >> 3)] = acc;
}

// ---------------- K5: segment softmax + aggregate + LN + residual + silu (one block / node) ----------------
__global__ __launch_bounds__(256) void node_aggregate(const float* __restrict__ conv_b,
                                                      const float* __restrict__ norm_g,
                                                      const float* __restrict__ norm_b,
                                                      float* __restrict__ dout,
                                                      size_t AL_OFF, int n)
{
    int node = blockIdx.x;
    int t = threadIdx.x;
    int lane = t & 31, warp = t >> 5;
    int start = g_off[node];
    int deg   = g_off[node + 1] - start;

    __shared__ float sh_red[32];
    __shared__ float sh_m[4], sh_inv[4];

    int h = t & 3;
    // phase A: segment max per head
    float mx = -1e30f;
    for (int j = t >> 2; j < deg; j += 64) {
        int eid = g_ceid[start + j];
        mx = fmaxf(mx, g_logits[(size_t)eid * 4 + h]);
    }
    mx = fmaxf(mx, __shfl_xor_sync(0xffffffffu, mx, 4));
    mx = fmaxf(mx, __shfl_xor_sync(0xffffffffu, mx, 8));
    mx = fmaxf(mx, __shfl_xor_sync(0xffffffffu, mx, 16));
    if (lane < 4) sh_red[warp * 4 + lane] = mx;
    __syncthreads();
    if (t < 4) {
        float m = sh_red[t];
        #pragma unroll
        for (int wq = 1; wq < 8; wq++) m = fmaxf(m, sh_red[wq * 4 + t]);
        sh_m[t] = m;
    }
    __syncthreads();

    // phase B: segment sum of exp
    float mh = sh_m[h];
    float sm = 0.0f;
    for (int j = t >> 2; j < deg; j += 64) {
        int eid = g_ceid[start + j];
        sm += expf(g_logits[(size_t)eid * 4 + h] - mh);
    }
    sm += __shfl_xor_sync(0xffffffffu, sm, 4);
    sm += __shfl_xor_sync(0xffffffffu, sm, 8);
    sm += __shfl_xor_sync(0xffffffffu, sm, 16);
    if (lane < 4) sh_red[warp * 4 + lane] = sm;
    __syncthreads();
    if (t < 4) {
        float s = 0.0f;
        #pragma unroll
        for (int wq = 0; wq < 8; wq++) s += sh_red[wq * 4 + t];
        sh_inv[t] = 1.0f / (s + 1e-16f);
    }
    __syncthreads();

    // alpha output write
    float invh = sh_inv[h];
    for (int j = t >> 2; j < deg; j += 64) {
        int eid = g_ceid[start + j];
        dout[AL_OFF + (size_t)eid * 4 + h] = expf(g_logits[(size_t)eid * 4 + h] - mh) * invh;
    }

    // phase C: weighted gather-accumulate (thread t <-> feature t)
    int hf = t >> 6;
    float mf = sh_m[hf], invf = sh_inv[hf];
    float acc = 0.0f;
    for (int j = 0; j < deg; j++) {
        int eid = __ldg(&g_ceid[start + j]);
        int s   = __ldg(&g_csrc[start + j]);
        float al = expf(__ldg(&g_logits[(size_t)eid * 4 + hf]) - mf) * invf;
        acc += al * __ldg(&g_xl[(size_t)s * 256 + t]);
    }

    // phase D: +conv_b, LayerNorm(256), +identity, silu -> act
    float vout = acc + conv_b[t];
    float sv = vout, sq = vout * vout;
    #pragma unroll
    for (int ss = 16; ss; ss >>= 1) {
        sv += __shfl_xor_sync(0xffffffffu, sv, ss);
        sq += __shfl_xor_sync(0xffffffffu, sq, ss);
    }
    __shared__ float shs[8], shq[8];
    __shared__ float sh_mean, sh_rstd;
    if (lane == 0) { shs[warp] = sv; shq[warp] = sq; }
    __syncthreads();
    if (t == 0) {
        float a = 0.0f, b = 0.0f;
        #pragma unroll
        for (int wq = 0; wq < 8; wq++) { a += shs[wq]; b += shq[wq]; }
        float mean = a * (1.0f / 256.0f);
        float var  = b * (1.0f / 256.0f) - mean * mean;
        sh_mean = mean;
        sh_rstd = rsqrtf(var + 1e-5f);
    }
    __syncthreads();
    float y = (vout - sh_mean) * sh_rstd * norm_g[t] + norm_b[t];
    float z = y + g_iden[(size_t)node * 256 + t];
    g_act[(size_t)node * 256 + t] = z / (1.0f + expf(-z));   // silu
}

// ---------------- host ----------------
extern "C" void kernel_launch(void* const* d_in, const int* in_sizes, int n_in,
                              void* d_out, int out_size)
{
    const float* x        = (const float*)d_in[0];
    const float* kpts     = (const float*)d_in[1];
    const float* pts3     = (const float*)d_in[2];
    const float* pe_w1    = (const float*)d_in[3];
    const float* pe_b1    = (const float*)d_in[4];
    const float* pe_g1    = (const float*)d_in[5];
    const float* pe_bn1   = (const float*)d_in[6];
    const float* pe_w2    = (const float*)d_in[7];
    const float* pe_b2    = (const float*)d_in[8];
    const float* pe_g2    = (const float*)d_in[9];
    const float* pe_bn2   = (const float*)d_in[10];
    const float* lin_l_w  = (const float*)d_in[11];
    const float* lin_l_b  = (const float*)d_in[12];
    const float* lin_r_w  = (const float*)d_in[13];
    const float* lin_r_b  = (const float*)d_in[14];
    const float* lin_e_w  = (const float*)d_in[15];
    const float* att      = (const float*)d_in[16];
    const float* conv_b   = (const float*)d_in[17];
    const float* norm_g   = (const float*)d_in[18];
    const float* norm_b   = (const float*)d_in[19];
    const float* res_w    = (const float*)d_in[20];
    const float* res_b    = (const float*)d_in[21];
    const float* proj_w   = (const float*)d_in[22];
    const float* proj_b   = (const float*)d_in[23];
    const int*   ei       = (const int*)d_in[24];

    int n = in_sizes[0] / XDIM;          // 50000
    int E = in_sizes[24] / 2;            // 800000
    float* out = (float*)d_out;
    size_t AL_OFF = (size_t)n * 256;
    size_t EA_OFF = AL_OFF + (size_t)E * 4;

    void *p_xcomb, *p_xl, *p_xr, *p_iden, *p_act;
    cudaGetSymbolAddress(&p_xcomb, g_xcomb);
    cudaGetSymbolAddress(&p_xl, g_xl);
    cudaGetSymbolAddress(&p_xr, g_xr);
    cudaGetSymbolAddress(&p_iden, g_iden);
    cudaGetSymbolAddress(&p_act, g_act);

    // 0) zero counters
    zero_counts<<<(n + 256) / 256, 256>>>(n);

    // 1) positional encoder + concat
    node_pre<<<(n + 7) / 8, 256>>>(x, kpts, pts3,
                                   pe_w1, pe_b1, pe_g1, pe_bn1,
                                   pe_w2, pe_b2, pe_g2, pe_bn2, n);

    // 2) dense transforms
    dim3 gg((n + 63) / 64, 4);
    gemm256<<<gg, 256>>>((const float*)p_xcomb, lin_l_w, lin_l_b, (float*)p_xl, n);
    gemm256<<<gg, 256>>>((const float*)p_xcomb, lin_r_w, lin_r_b, (float*)p_xr, n);
    gemm256<<<gg, 256>>>((const float*)p_xcomb, res_w,   res_b,   (float*)p_iden, n);

    // 3) CSR by destination
    count_deg<<<(E + 255) / 256, 256>>>(ei, E);
    scan_offsets<<<1, 1024>>>(n);
    fill_csr<<<(E + 255) / 256, 256>>>(ei, E);

    // 4) edge attrs + logits
    edge_logits<<<(E + 7) / 8, 256>>>(ei, lin_e_w, att, out, EA_OFF, E);

    // 5) segment softmax + aggregate + epilogue
    node_aggregate<<<n, 256>>>(conv_b, norm_g, norm_b, out, AL_OFF, n);

    // 6) final projection -> out
    gemm256<<<gg, 256>>>((const float*)p_act, proj_w, proj_b, out, n);
}

// round 7
// speedup vs baseline: 1.1514x; 1.1514x over previous
#include <cuda_runtime.h>
#include <cstdint>
#include <cstddef>

// ---------------- problem constants ----------------
#define NMAX 50176
#define EMAX 800000
#define HF   256
#define CIN  256
#define XDIM 192

// ---------------- device scratch (static, no allocation) ----------------
__device__ float g_xcomb[(size_t)NMAX * 256];
__device__ float g_xl   [(size_t)NMAX * 256];
__device__ float g_xr   [(size_t)NMAX * 256];
__device__ float g_iden [(size_t)NMAX * 256];
__device__ float g_act  [(size_t)NMAX * 256];
__device__ float g_nu   [(size_t)NMAX * 2];
__device__ float g_logits[(size_t)EMAX * 4];
__device__ int   g_deg [NMAX + 1];
__device__ int   g_off [NMAX + 1];
__device__ int   g_fill[NMAX + 1];
__device__ int   g_ceid[EMAX];
__device__ int   g_csrc[EMAX];

// ---------------- helpers ----------------
__device__ __forceinline__ float wredsum(float v) {
    #pragma unroll
    for (int s = 16; s; s >>= 1) v += __shfl_xor_sync(0xffffffffu, v, s);
    return v;
}

// ---------------- K0: zero CSR counters ----------------
__global__ void zero_counts(int n) {
    int i = blockIdx.x * blockDim.x + threadIdx.x;
    if (i <= n) { g_deg[i] = 0; g_fill[i] = 0; }
}

// ---------------- K1: positional encoder + concat (one warp / node) ----------------
__global__ void node_pre(const float* __restrict__ x, const float* __restrict__ kpts,
                         const float* __restrict__ pts3,
                         const float* __restrict__ pe_w1, const float* __restrict__ pe_b1,
                         const float* __restrict__ pe_g1, const float* __restrict__ pe_bn1,
                         const float* __restrict__ pe_w2, const float* __restrict__ pe_b2,
                         const float* __restrict__ pe_g2, const float* __restrict__ pe_bn2,
                         int n)
{
    int node = (blockIdx.x * blockDim.x + threadIdx.x) >> 5;
    int lane = threadIdx.x & 31;
    if (node >= n) return;

    float u = kpts[2 * node]     * (1.0f / 1216.0f);
    float v = kpts[2 * node + 1] * (1.0f / 352.0f);
    float d = pts3[3 * node + 2];
    d = fminf(fmaxf(d, 0.1f), 100.0f);
    if (lane == 0) { g_nu[2 * node] = u; g_nu[2 * node + 1] = v; }

    float h1 = pe_b1[lane] + pe_w1[lane * 3] * u + pe_w1[lane * 3 + 1] * v + pe_w1[lane * 3 + 2] * d;
    float m  = wredsum(h1) * (1.0f / 32.0f);
    float c  = h1 - m;
    float vr = wredsum(c * c) * (1.0f / 32.0f);
    float y  = c * rsqrtf(vr + 1e-5f) * pe_g1[lane] + pe_bn1[lane];
    y = y / (1.0f + expf(-y));

    float o0 = pe_b2[lane], o1 = pe_b2[lane + 32];
    #pragma unroll
    for (int k = 0; k < 32; k++) {
        float hk = __shfl_sync(0xffffffffu, y, k);
        o0 += pe_w2[lane * 32 + k] * hk;
        o1 += pe_w2[(lane + 32) * 32 + k] * hk;
    }
    float m2 = wredsum(o0 + o1) * (1.0f / 64.0f);
    float c0 = o0 - m2, c1 = o1 - m2;
    float v2 = wredsum(c0 * c0 + c1 * c1) * (1.0f / 64.0f);
    float r  = rsqrtf(v2 + 1e-5f);
    float p0 = c0 * r * pe_g2[lane]      + pe_bn2[lane];
    float p1 = c1 * r * pe_g2[lane + 32] + pe_bn2[lane + 32];

    size_t base = (size_t)node * 256;
    g_xcomb[base + 192 + lane] = p0;
    g_xcomb[base + 224 + lane] = p1;
    #pragma unroll
    for (int i = lane; i < XDIM; i += 32)
        g_xcomb[base + i] = x[(size_t)node * XDIM + i];
}

// ---------------- K2: 128x128 tiled fp32 GEMM, 8x8 microtile, double buffered ----
// C[M,256] = A[M,256] @ W[256,256]^T + bias
#define BM 128
#define BN 128
#define BK 16
#define APAD 132

__global__ __launch_bounds__(256) void gemm256(const float* __restrict__ A,
                                               const float* __restrict__ W,
                                               const float* __restrict__ bias,
                                               float* __restrict__ C, int M)
{
    __shared__ __align__(16) float As[2][BK][APAD];
    __shared__ __align__(16) float Bs[2][BK][APAD];

    int tid = threadIdx.x;
    int m0 = blockIdx.x * BM, f0 = blockIdx.y * BN;
    int lr = tid >> 2;            // 0..63
    int kg = (tid & 3) * 4;       // 0,4,8,12

    const float* Ap1 = A + (size_t)(m0 + lr) * 256 + kg;
    const float* Ap2 = Ap1 + (size_t)64 * 256;
    const float* Wp1 = W + (size_t)(f0 + lr) * 256 + kg;
    const float* Wp2 = Wp1 + (size_t)64 * 256;
    bool av1 = (m0 + lr) < M;
    bool av2 = (m0 + lr + 64) < M;

    const float4 fz = make_float4(0.f, 0.f, 0.f, 0.f);
    float4 ra1 = av1 ? *(const float4*)Ap1 : fz;
    float4 ra2 = av2 ? *(const float4*)Ap2 : fz;
    float4 rb1 = *(const float4*)Wp1;
    float4 rb2 = *(const float4*)Wp2;

    As[0][kg + 0][lr] = ra1.x; As[0][kg + 1][lr] = ra1.y; As[0][kg + 2][lr] = ra1.z; As[0][kg + 3][lr] = ra1.w;
    As[0][kg + 0][64 + lr] = ra2.x; As[0][kg + 1][64 + lr] = ra2.y; As[0][kg + 2][64 + lr] = ra2.z; As[0][kg + 3][64 + lr] = ra2.w;
    Bs[0][kg + 0][lr] = rb1.x; Bs[0][kg + 1][lr] = rb1.y; Bs[0][kg + 2][lr] = rb1.z; Bs[0][kg + 3][lr] = rb1.w;
    Bs[0][kg + 0][64 + lr] = rb2.x; Bs[0][kg + 1][64 + lr] = rb2.y; Bs[0][kg + 2][64 + lr] = rb2.z; Bs[0][kg + 3][64 + lr] = rb2.w;
    __syncthreads();

    float acc[8][8] = {};
    int tx = tid & 15, ty = tid >> 4;

    #pragma unroll 1
    for (int kt = 0; kt < 256 / BK; kt++) {
        int cur = kt & 1, nxt = cur ^ 1;
        if (kt < 256 / BK - 1) {
            int off = (kt + 1) * BK;
            ra1 = av1 ? *(const float4*)(Ap1 + off) : fz;
            ra2 = av2 ? *(const float4*)(Ap2 + off) : fz;
            rb1 = *(const float4*)(Wp1 + off);
            rb2 = *(const float4*)(Wp2 + off);
        }
        #pragma unroll
        for (int k = 0; k < BK; k++) {
            float4 a0 = *(const float4*)&As[cur][k][ty * 4];
            float4 a1 = *(const float4*)&As[cur][k][64 + ty * 4];
            float4 b0 = *(const float4*)&Bs[cur][k][tx * 4];
            float4 b1 = *(const float4*)&Bs[cur][k][64 + tx * 4];
            float a[8] = {a0.x, a0.y, a0.z, a0.w, a1.x, a1.y, a1.z, a1.w};
            float b[8] = {b0.x, b0.y, b0.z, b0.w, b1.x, b1.y, b1.z, b1.w};
            #pragma unroll
            for (int i = 0; i < 8; i++)
                #pragma unroll
                for (int j = 0; j < 8; j++)
                    acc[i][j] += a[i] * b[j];
        }
        if (kt < 256 / BK - 1) {
            As[nxt][kg + 0][lr] = ra1.x; As[nxt][kg + 1][lr] = ra1.y; As[nxt][kg + 2][lr] = ra1.z; As[nxt][kg + 3][lr] = ra1.w;
            As[nxt][kg + 0][64 + lr] = ra2.x; As[nxt][kg + 1][64 + lr] = ra2.y; As[nxt][kg + 2][64 + lr] = ra2.z; As[nxt][kg + 3][64 + lr] = ra2.w;
            Bs[nxt][kg + 0][lr] = rb1.x; Bs[nxt][kg + 1][lr] = rb1.y; Bs[nxt][kg + 2][lr] = rb1.z; Bs[nxt][kg + 3][lr] = rb1.w;
            Bs[nxt][kg + 0][64 + lr] = rb2.x; Bs[nxt][kg + 1][64 + lr] = rb2.y; Bs[nxt][kg + 2][64 + lr] = rb2.z; Bs[nxt][kg + 3][64 + lr] = rb2.w;
            __syncthreads();
        }
    }

    float bj0[4], bj1[4];
    #pragma unroll
    for (int j = 0; j < 4; j++) {
        bj0[j] = bias[f0 + tx * 4 + j];
        bj1[j] = bias[f0 + 64 + tx * 4 + j];
    }
    #pragma unroll
    for (int i = 0; i < 8; i++) {
        int row = m0 + ((i < 4) ? (ty * 4 + i) : (64 + ty * 4 + i - 4));
        if (row < M) {
            float4 v0 = make_float4(acc[i][0] + bj0[0], acc[i][1] + bj0[1],
                                    acc[i][2] + bj0[2], acc[i][3] + bj0[3]);
            float4 v1 = make_float4(acc[i][4] + bj1[0], acc[i][5] + bj1[1],
                                    acc[i][6] + bj1[2], acc[i][7] + bj1[3]);
            *(float4*)&C[(size_t)row * 256 + f0 + tx * 4]      = v0;
            *(float4*)&C[(size_t)row * 256 + f0 + 64 + tx * 4] = v1;
        }
    }
}

// ---------------- K3: CSR build ----------------
__global__ void count_deg(const int* __restrict__ ei, int E) {
    int i = blockIdx.x * blockDim.x + threadIdx.x;
    if (i < E) atomicAdd(&g_deg[ei[E + i]], 1);
}

__global__ void scan_offsets(int n) {
    __shared__ int wsum[32];
    __shared__ int carry;
    int t = threadIdx.x, lane = t & 31, w = t >> 5;
    if (t == 0) { carry = 0; g_off[0] = 0; }
    __syncthreads();
    for (int base = 0; base < n; base += 1024) {
        int i = base + t;
        int v = (i < n) ? g_deg[i] : 0;
        int sc = v;
        #pragma unroll
        for (int s = 1; s < 32; s <<= 1) {
            int xv = __shfl_up_sync(0xffffffffu, sc, s);
            if (lane >= s) sc += xv;
        }
        if (lane == 31) wsum[w] = sc;
        __syncthreads();
        if (w == 0) {
            int ws = wsum[lane];
            #pragma unroll
            for (int s = 1; s < 32; s <<= 1) {
                int xv = __shfl_up_sync(0xffffffffu, ws, s);
                if (lane >= s) ws += xv;
            }
            wsum[lane] = ws;
        }
        __syncthreads();
        int add = carry + (w ? wsum[w - 1] : 0);
        if (i < n) g_off[i + 1] = add + sc;
        int total = wsum[31];
        __syncthreads();
        if (t == 0) carry += total;
        __syncthreads();
    }
}

__global__ void fill_csr(const int* __restrict__ ei, int E) {
    int i = blockIdx.x * blockDim.x + threadIdx.x;
    if (i < E) {
        int d = ei[E + i];
        int p = g_off[d] + atomicAdd(&g_fill[d], 1);
        g_ceid[p] = i;
        g_csrc[p] = ei[i];
    }
}

// ---------------- K4: edge attrs + attention logits (one warp / edge) ----------------
__global__ __launch_bounds__(256) void edge_logits(const int* __restrict__ ei,
                                                   const float* __restrict__ ew,
                                                   const float* __restrict__ att,
                                                   float* __restrict__ dout,
                                                   size_t EA_OFF, int E)
{
    int w = (blockIdx.x * blockDim.x + threadIdx.x) >> 5;
    if (w >= E) return;
    int lane = threadIdx.x & 31;
    int src = __ldg(&ei[w]);
    int dst = __ldg(&ei[E + w]);

    float a0 = g_nu[2 * dst]     - g_nu[2 * src];
    float a1 = g_nu[2 * dst + 1] - g_nu[2 * src + 1];
    float a2 = sqrtf(a0 * a0 + a1 * a1);
    if (lane == 0) {
        dout[EA_OFF + (size_t)w * 3]     = a0;
        dout[EA_OFF + (size_t)w * 3 + 1] = a1;
        dout[EA_OFF + (size_t)w * 3 + 2] = a2;
    }

    int f0 = lane * 8;
    const float* xl = &g_xl[(size_t)src * 256 + f0];
    const float* xr = &g_xr[(size_t)dst * 256 + f0];
    float4 l0 = *(const float4*)xl, l1 = *(const float4*)(xl + 4);
    float4 r0 = *(const float4*)xr, r1 = *(const float4*)(xr + 4);
    float vals[8] = { l0.x + r0.x, l0.y + r0.y, l0.z + r0.z, l0.w + r0.w,
                      l1.x + r1.x, l1.y + r1.y, l1.z + r1.z, l1.w + r1.w };
    float acc = 0.0f;
    #pragma unroll
    for (int i = 0; i < 8; i++) {
        int f = f0 + i;
        float vv = vals[i] + __ldg(&ew[f * 3]) * a0 + __ldg(&ew[f * 3 + 1]) * a1 + __ldg(&ew[f * 3 + 2]) * a2;
        vv = vv > 0.0f ? vv : 0.2f * vv;
        acc += vv * __ldg(&att[f]);
    }
    acc += __shfl_xor_sync(0xffffffffu, acc, 1);
    acc += __shfl_xor_sync(0xffffffffu, acc, 2);
    acc += __shfl_xor_sync(0xffffffffu, acc, 4);
    if ((lane & 7) == 0) g_logits[(size_t)w * 4 + (lane >> 3)] = acc;
}

// ---------------- K5: segment softmax + aggregate + LN + residual + silu ----------
// exp computed ONCE per (edge,head); alpha stored in-place into g_logits; the
// gather pass is pure FFMA over smem-staged (src, alpha) chunks.
__global__ __launch_bounds__(256) void node_aggregate(const float* __restrict__ conv_b,
                                                      const float* __restrict__ norm_g,
                                                      const float* __restrict__ norm_b,
                                                      float* __restrict__ dout,
                                                      size_t AL_OFF, int n)
{
    int node = blockIdx.x;
    int t = threadIdx.x;
    int lane = t & 31, warp = t >> 5;
    int start = g_off[node];
    int deg   = g_off[node + 1] - start;

    __shared__ float sh_red[32];
    __shared__ float sh_m[4], sh_inv[4];
    __shared__ int   s_src[64];
    __shared__ float s_al[64 * 4];

    int h = t & 3;
    // phase A: segment max per head
    float mx = -1e30f;
    for (int j = t >> 2; j < deg; j += 64) {
        int eid = g_ceid[start + j];
        mx = fmaxf(mx, g_logits[(size_t)eid * 4 + h]);
    }
    mx = fmaxf(mx, __shfl_xor_sync(0xffffffffu, mx, 4));
    mx = fmaxf(mx, __shfl_xor_sync(0xffffffffu, mx, 8));
    mx = fmaxf(mx, __shfl_xor_sync(0xffffffffu, mx, 16));
    if (lane < 4) sh_red[warp * 4 + lane] = mx;
    __syncthreads();
    if (t < 4) {
        float m = sh_red[t];
        #pragma unroll
        for (int wq = 1; wq < 8; wq++) m = fmaxf(m, sh_red[wq * 4 + t]);
        sh_m[t] = m;
    }
    __syncthreads();

    // phase B: exp once per (edge,head); store e in-place; reduce sum
    float mh = sh_m[h];
    float sm = 0.0f;
    for (int j = t >> 2; j < deg; j += 64) {
        int eid = g_ceid[start + j];
        float e = expf(g_logits[(size_t)eid * 4 + h] - mh);
        g_logits[(size_t)eid * 4 + h] = e;
        sm += e;
    }
    sm += __shfl_xor_sync(0xffffffffu, sm, 4);
    sm += __shfl_xor_sync(0xffffffffu, sm, 8);
    sm += __shfl_xor_sync(0xffffffffu, sm, 16);
    if (lane < 4) sh_red[warp * 4 + lane] = sm;
    __syncthreads();
    if (t < 4) {
        float s = 0.0f;
        #pragma unroll
        for (int wq = 0; wq < 8; wq++) s += sh_red[wq * 4 + t];
        sh_inv[t] = 1.0f / (s + 1e-16f);
    }
    __syncthreads();

    // alpha finalize: scale in-place + write alpha output
    float invh = sh_inv[h];
    for (int j = t >> 2; j < deg; j += 64) {
        int eid = g_ceid[start + j];
        float al = g_logits[(size_t)eid * 4 + h] * invh;
        g_logits[(size_t)eid * 4 + h] = al;
        dout[AL_OFF + (size_t)eid * 4 + h] = al;
    }
    __syncthreads();

    // phase C: weighted gather-accumulate over smem-staged chunks (pure FFMA)
    int hf = t >> 6;
    float acc = 0.0f;
    for (int c0 = 0; c0 < deg; c0 += 64) {
        int cnt = min(64, deg - c0);
        if (t < cnt) s_src[t] = g_csrc[start + c0 + t];
        if (t < cnt * 4) {
            int jj = t >> 2, hh = t & 3;
            s_al[jj * 4 + hh] = g_logits[(size_t)g_ceid[start + c0 + jj] * 4 + hh];
        }
        __syncthreads();
        int jj = 0;
        for (; jj + 4 <= cnt; jj += 4) {
            int s0 = s_src[jj], s1 = s_src[jj + 1], s2 = s_src[jj + 2], s3 = s_src[jj + 3];
            float a0 = s_al[jj * 4 + hf], a1 = s_al[(jj + 1) * 4 + hf];
            float a2 = s_al[(jj + 2) * 4 + hf], a3 = s_al[(jj + 3) * 4 + hf];
            float x0 = __ldg(&g_xl[(size_t)s0 * 256 + t]);
            float x1 = __ldg(&g_xl[(size_t)s1 * 256 + t]);
            float x2 = __ldg(&g_xl[(size_t)s2 * 256 + t]);
            float x3 = __ldg(&g_xl[(size_t)s3 * 256 + t]);
            acc += a0 * x0 + a1 * x1 + a2 * x2 + a3 * x3;
        }
        for (; jj < cnt; jj++)
            acc += s_al[jj * 4 + hf] * __ldg(&g_xl[(size_t)s_src[jj] * 256 + t]);
        __syncthreads();
    }

    // phase D: +conv_b, LayerNorm(256), +identity, silu -> act
    float vout = acc + conv_b[t];
    float sv = vout, sq = vout * vout;
    #pragma unroll
    for (int ss = 16; ss; ss >>= 1) {
        sv += __shfl_xor_sync(0xffffffffu, sv, ss);
        sq += __shfl_xor_sync(0xffffffffu, sq, ss);
    }
    __shared__ float shs[8], shq[8];
    __shared__ float sh_mean, sh_rstd;
    if (lane == 0) { shs[warp] = sv; shq[warp] = sq; }
    __syncthreads();
    if (t == 0) {
        float a = 0.0f, b = 0.0f;
        #pragma unroll
        for (int wq = 0; wq < 8; wq++) { a += shs[wq]; b += shq[wq]; }
        float mean = a * (1.0f / 256.0f);
        float var  = b * (1.0f / 256.0f) - mean * mean;
        sh_mean = mean;
        sh_rstd = rsqrtf(var + 1e-5f);
    }
    __syncthreads();
    float y = (vout - sh_mean) * sh_rstd * norm_g[t] + norm_b[t];
    float z = y + g_iden[(size_t)node * 256 + t];
    g_act[(size_t)node * 256 + t] = z / (1.0f + expf(-z));
}

// ---------------- host ----------------
extern "C" void kernel_launch(void* const* d_in, const int* in_sizes, int n_in,
                              void* d_out, int out_size)
{
    const float* x        = (const float*)d_in[0];
    const float* kpts     = (const float*)d_in[1];
    const float* pts3     = (const float*)d_in[2];
    const float* pe_w1    = (const float*)d_in[3];
    const float* pe_b1    = (const float*)d_in[4];
    const float* pe_g1    = (const float*)d_in[5];
    const float* pe_bn1   = (const float*)d_in[6];
    const float* pe_w2    = (const float*)d_in[7];
    const float* pe_b2    = (const float*)d_in[8];
    const float* pe_g2    = (const float*)d_in[9];
    const float* pe_bn2   = (const float*)d_in[10];
    const float* lin_l_w  = (const float*)d_in[11];
    const float* lin_l_b  = (const float*)d_in[12];
    const float* lin_r_w  = (const float*)d_in[13];
    const float* lin_r_b  = (const float*)d_in[14];
    const float* lin_e_w  = (const float*)d_in[15];
    const float* att      = (const float*)d_in[16];
    const float* conv_b   = (const float*)d_in[17];
    const float* norm_g   = (const float*)d_in[18];
    const float* norm_b   = (const float*)d_in[19];
    const float* res_w    = (const float*)d_in[20];
    const float* res_b    = (const float*)d_in[21];
    const float* proj_w   = (const float*)d_in[22];
    const float* proj_b   = (const float*)d_in[23];
    const int*   ei       = (const int*)d_in[24];

    int n = in_sizes[0] / XDIM;          // 50000
    int E = in_sizes[24] / 2;            // 800000
    float* out = (float*)d_out;
    size_t AL_OFF = (size_t)n * 256;
    size_t EA_OFF = AL_OFF + (size_t)E * 4;

    void *p_xcomb, *p_xl, *p_xr, *p_iden, *p_act;
    cudaGetSymbolAddress(&p_xcomb, g_xcomb);
    cudaGetSymbolAddress(&p_xl, g_xl);
    cudaGetSymbolAddress(&p_xr, g_xr);
    cudaGetSymbolAddress(&p_iden, g_iden);
    cudaGetSymbolAddress(&p_act, g_act);

    // 0) zero counters
    zero_counts<<<(n + 256) / 256, 256>>>(n);

    // 1) positional encoder + concat
    node_pre<<<(n + 7) / 8, 256>>>(x, kpts, pts3,
                                   pe_w1, pe_b1, pe_g1, pe_bn1,
                                   pe_w2, pe_b2, pe_g2, pe_bn2, n);

    // 2) dense transforms (128x128 tiles)
    dim3 gg((n + BM - 1) / BM, 256 / BN);
    gemm256<<<gg, 256>>>((const float*)p_xcomb, lin_l_w, lin_l_b, (float*)p_xl, n);
    gemm256<<<gg, 256>>>((const float*)p_xcomb, lin_r_w, lin_r_b, (float*)p_xr, n);
    gemm256<<<gg, 256>>>((const float*)p_xcomb, res_w,   res_b,   (float*)p_iden, n);

    // 3) CSR by destination
    count_deg<<<(E + 255) / 256, 256>>>(ei, E);
    scan_offsets<<<1, 1024>>>(n);
    fill_csr<<<(E + 255) / 256, 256>>>(ei, E);

    // 4) edge attrs + logits
    edge_logits<<<(E + 7) / 8, 256>>>(ei, lin_e_w, att, out, EA_OFF, E);

    // 5) segment softmax + aggregate + epilogue
    node_aggregate<<<n, 256>>>(conv_b, norm_g, norm_b, out, AL_OFF, n);

    // 6) final projection -> out
    gemm256<<<gg, 256>>>((const float*)p_act, proj_w, proj_b, out, n);
}

// round 8
// speedup vs baseline: 1.8634x; 1.6183x over previous
#include <cuda_runtime.h>
#include <cstdint>
#include <cstddef>

// ---------------- problem constants ----------------
#define NMAX 50176
#define EMAX 800000
#define HF   256
#define CIN  256
#define XDIM 192
#define DEGC 512          // smem edge capacity per node (fallback beyond)

// ---------------- device scratch (static, no allocation) ----------------
__device__ float g_xcomb[(size_t)NMAX * 256];
__device__ float g_xl   [(size_t)NMAX * 256];
__device__ float g_xr   [(size_t)NMAX * 256];
__device__ float g_iden [(size_t)NMAX * 256];
__device__ float g_act  [(size_t)NMAX * 256];
__device__ float g_nu   [(size_t)NMAX * 2];
__device__ float g_logits[(size_t)EMAX * 4];   // only used in deg>DEGC fallback
__device__ int   g_deg [NMAX + 1];
__device__ int   g_off [NMAX + 1];
__device__ int   g_fill[NMAX + 1];
__device__ int   g_ceid[EMAX];
__device__ int   g_csrc[EMAX];

// ---------------- helpers ----------------
__device__ __forceinline__ float wredsum(float v) {
    #pragma unroll
    for (int s = 16; s; s >>= 1) v += __shfl_xor_sync(0xffffffffu, v, s);
    return v;
}

// ---------------- K0: zero CSR counters ----------------
__global__ void zero_counts(int n) {
    int i = blockIdx.x * blockDim.x + threadIdx.x;
    if (i <= n) { g_deg[i] = 0; g_fill[i] = 0; }
}

// ---------------- K1: positional encoder + concat (one warp / node) ----------------
// pe_w2 staged TRANSPOSED in smem -> conflict-free reads (was 32-line L1 replays)
__global__ __launch_bounds__(256) void node_pre(
        const float* __restrict__ x, const float* __restrict__ kpts,
        const float* __restrict__ pts3,
        const float* __restrict__ pe_w1, const float* __restrict__ pe_b1,
        const float* __restrict__ pe_g1, const float* __restrict__ pe_bn1,
        const float* __restrict__ pe_w2, const float* __restrict__ pe_b2,
        const float* __restrict__ pe_g2, const float* __restrict__ pe_bn2,
        int n)
{
    __shared__ float s_w2t[32][65];   // [k][out]
    int t = threadIdx.x;
    for (int i = t; i < 2048; i += 256) {
        int out = i >> 5, k = i & 31;
        s_w2t[k][out] = pe_w2[i];     // pe_w2[out*32+k], coalesced read
    }
    __syncthreads();

    int node = (blockIdx.x * 256 + t) >> 5;
    int lane = t & 31;
    if (node >= n) return;

    float u = kpts[2 * node]     * (1.0f / 1216.0f);
    float v = kpts[2 * node + 1] * (1.0f / 352.0f);
    float d = pts3[3 * node + 2];
    d = fminf(fmaxf(d, 0.1f), 100.0f);
    if (lane == 0) { g_nu[2 * node] = u; g_nu[2 * node + 1] = v; }

    float h1 = pe_b1[lane] + pe_w1[lane * 3] * u + pe_w1[lane * 3 + 1] * v + pe_w1[lane * 3 + 2] * d;
    float m  = wredsum(h1) * (1.0f / 32.0f);
    float c  = h1 - m;
    float vr = wredsum(c * c) * (1.0f / 32.0f);
    float y  = c * rsqrtf(vr + 1e-5f) * pe_g1[lane] + pe_bn1[lane];
    y = y / (1.0f + expf(-y));

    float o0 = pe_b2[lane], o1 = pe_b2[lane + 32];
    #pragma unroll
    for (int k = 0; k < 32; k++) {
        float hk = __shfl_sync(0xffffffffu, y, k);
        o0 += s_w2t[k][lane]      * hk;
        o1 += s_w2t[k][lane + 32] * hk;
    }
    float m2 = wredsum(o0 + o1) * (1.0f / 64.0f);
    float c0 = o0 - m2, c1 = o1 - m2;
    float v2 = wredsum(c0 * c0 + c1 * c1) * (1.0f / 64.0f);
    float r  = rsqrtf(v2 + 1e-5f);
    float p0 = c0 * r * pe_g2[lane]      + pe_bn2[lane];
    float p1 = c1 * r * pe_g2[lane + 32] + pe_bn2[lane + 32];

    size_t base = (size_t)node * 256;
    g_xcomb[base + 192 + lane] = p0;
    g_xcomb[base + 224 + lane] = p1;
    #pragma unroll
    for (int i = lane; i < XDIM; i += 32)
        g_xcomb[base + i] = x[(size_t)node * XDIM + i];
}

// ---------------- K2: 128x128 tiled fp32 GEMM, 8x8 microtile, double buffered ----
#define BM 128
#define BN 128
#define BK 16
#define APAD 132

__global__ __launch_bounds__(256) void gemm256(const float* __restrict__ A,
                                               const float* __restrict__ W,
                                               const float* __restrict__ bias,
                                               float* __restrict__ C, int M)
{
    __shared__ __align__(16) float As[2][BK][APAD];
    __shared__ __align__(16) float Bs[2][BK][APAD];

    int tid = threadIdx.x;
    int m0 = blockIdx.x * BM, f0 = blockIdx.y * BN;
    int lr = tid >> 2;
    int kg = (tid & 3) * 4;

    const float* Ap1 = A + (size_t)(m0 + lr) * 256 + kg;
    const float* Ap2 = Ap1 + (size_t)64 * 256;
    const float* Wp1 = W + (size_t)(f0 + lr) * 256 + kg;
    const float* Wp2 = Wp1 + (size_t)64 * 256;
    bool av1 = (m0 + lr) < M;
    bool av2 = (m0 + lr + 64) < M;

    const float4 fz = make_float4(0.f, 0.f, 0.f, 0.f);
    float4 ra1 = av1 ? *(const float4*)Ap1 : fz;
    float4 ra2 = av2 ? *(const float4*)Ap2 : fz;
    float4 rb1 = *(const float4*)Wp1;
    float4 rb2 = *(const float4*)Wp2;

    As[0][kg + 0][lr] = ra1.x; As[0][kg + 1][lr] = ra1.y; As[0][kg + 2][lr] = ra1.z; As[0][kg + 3][lr] = ra1.w;
    As[0][kg + 0][64 + lr] = ra2.x; As[0][kg + 1][64 + lr] = ra2.y; As[0][kg + 2][64 + lr] = ra2.z; As[0][kg + 3][64 + lr] = ra2.w;
    Bs[0][kg + 0][lr] = rb1.x; Bs[0][kg + 1][lr] = rb1.y; Bs[0][kg + 2][lr] = rb1.z; Bs[0][kg + 3][lr] = rb1.w;
    Bs[0][kg + 0][64 + lr] = rb2.x; Bs[0][kg + 1][64 + lr] = rb2.y; Bs[0][kg + 2][64 + lr] = rb2.z; Bs[0][kg + 3][64 + lr] = rb2.w;
    __syncthreads();

    float acc[8][8] = {};
    int tx = tid & 15, ty = tid >> 4;

    #pragma unroll 1
    for (int kt = 0; kt < 256 / BK; kt++) {
        int cur = kt & 1, nxt = cur ^ 1;
        if (kt < 256 / BK - 1) {
            int off = (kt + 1) * BK;
            ra1 = av1 ? *(const float4*)(Ap1 + off) : fz;
            ra2 = av2 ? *(const float4*)(Ap2 + off) : fz;
            rb1 = *(const float4*)(Wp1 + off);
            rb2 = *(const float4*)(Wp2 + off);
        }
        #pragma unroll
        for (int k = 0; k < BK; k++) {
            float4 a0 = *(const float4*)&As[cur][k][ty * 4];
            float4 a1 = *(const float4*)&As[cur][k][64 + ty * 4];
            float4 b0 = *(const float4*)&Bs[cur][k][tx * 4];
            float4 b1 = *(const float4*)&Bs[cur][k][64 + tx * 4];
            float a[8] = {a0.x, a0.y, a0.z, a0.w, a1.x, a1.y, a1.z, a1.w};
            float b[8] = {b0.x, b0.y, b0.z, b0.w, b1.x, b1.y, b1.z, b1.w};
            #pragma unroll
            for (int i = 0; i < 8; i++)
                #pragma unroll
                for (int j = 0; j < 8; j++)
                    acc[i][j] += a[i] * b[j];
        }
        if (kt < 256 / BK - 1) {
            As[nxt][kg + 0][lr] = ra1.x; As[nxt][kg + 1][lr] = ra1.y; As[nxt][kg + 2][lr] = ra1.z; As[nxt][kg + 3][lr] = ra1.w;
            As[nxt][kg + 0][64 + lr] = ra2.x; As[nxt][kg + 1][64 + lr] = ra2.y; As[nxt][kg + 2][64 + lr] = ra2.z; As[nxt][kg + 3][64 + lr] = ra2.w;
            Bs[nxt][kg + 0][lr] = rb1.x; Bs[nxt][kg + 1][lr] = rb1.y; Bs[nxt][kg + 2][lr] = rb1.z; Bs[nxt][kg + 3][lr] = rb1.w;
            Bs[nxt][kg + 0][64 + lr] = rb2.x; Bs[nxt][kg + 1][64 + lr] = rb2.y; Bs[nxt][kg + 2][64 + lr] = rb2.z; Bs[nxt][kg + 3][64 + lr] = rb2.w;
            __syncthreads();
        }
    }

    float bj0[4], bj1[4];
    #pragma unroll
    for (int j = 0; j < 4; j++) {
        bj0[j] = bias[f0 + tx * 4 + j];
        bj1[j] = bias[f0 + 64 + tx * 4 + j];
    }
    #pragma unroll
    for (int i = 0; i < 8; i++) {
        int row = m0 + ((i < 4) ? (ty * 4 + i) : (64 + ty * 4 + i - 4));
        if (row < M) {
            float4 v0 = make_float4(acc[i][0] + bj0[0], acc[i][1] + bj0[1],
                                    acc[i][2] + bj0[2], acc[i][3] + bj0[3]);
            float4 v1 = make_float4(acc[i][4] + bj1[0], acc[i][5] + bj1[1],
                                    acc[i][6] + bj1[2], acc[i][7] + bj1[3]);
            *(float4*)&C[(size_t)row * 256 + f0 + tx * 4]      = v0;
            *(float4*)&C[(size_t)row * 256 + f0 + 64 + tx * 4] = v1;
        }
    }
}

// ---------------- K3: CSR build ----------------
__global__ void count_deg(const int* __restrict__ ei, int E) {
    int i = blockIdx.x * blockDim.x + threadIdx.x;
    if (i < E) atomicAdd(&g_deg[ei[E + i]], 1);
}

__global__ void scan_offsets(int n) {
    __shared__ int wsum[32];
    __shared__ int carry;
    int t = threadIdx.x, lane = t & 31, w = t >> 5;
    if (t == 0) { carry = 0; g_off[0] = 0; }
    __syncthreads();
    for (int base = 0; base < n; base += 1024) {
        int i = base + t;
        int v = (i < n) ? g_deg[i] : 0;
        int sc = v;
        #pragma unroll
        for (int s = 1; s < 32; s <<= 1) {
            int xv = __shfl_up_sync(0xffffffffu, sc, s);
            if (lane >= s) sc += xv;
        }
        if (lane == 31) wsum[w] = sc;
        __syncthreads();
        if (w == 0) {
            int ws = wsum[lane];
            #pragma unroll
            for (int s = 1; s < 32; s <<= 1) {
                int xv = __shfl_up_sync(0xffffffffu, ws, s);
                if (lane >= s) ws += xv;
            }
            wsum[lane] = ws;
        }
        __syncthreads();
        int add = carry + (w ? wsum[w - 1] : 0);
        if (i < n) g_off[i + 1] = add + sc;
        int total = wsum[31];
        __syncthreads();
        if (t == 0) carry += total;
        __syncthreads();
    }
}

__global__ void fill_csr(const int* __restrict__ ei, int E) {
    int i = blockIdx.x * blockDim.x + threadIdx.x;
    if (i < E) {
        int d = ei[E + i];
        int p = g_off[d] + atomicAdd(&g_fill[d], 1);
        g_ceid[p] = i;
        g_csrc[p] = ei[i];
    }
}

// ---------------- K4: FUSED per-node kernel -------------------------------
// edge attrs + logits (warp/edge, smem SoA weights) + segment softmax (smem)
// + alpha write + weighted gather + LN + residual + silu.
__global__ __launch_bounds__(256) void fused_node(
        const float* __restrict__ lin_e_w, const float* __restrict__ att,
        const float* __restrict__ conv_b, const float* __restrict__ norm_g,
        const float* __restrict__ norm_b, float* __restrict__ dout,
        size_t AL_OFF, size_t EA_OFF, int n)
{
    __shared__ __align__(16) float s_xr[256];
    __shared__ __align__(16) float s_ew[768];     // SoA: s_ew[c*256+f]
    __shared__ __align__(16) float s_att[256];
    __shared__ int   s_src[DEGC];
    __shared__ int   s_eid[DEGC];
    __shared__ __align__(16) float s_logit[DEGC * 4];
    __shared__ float sh_red[32], sh_m[4], sh_inv[4];
    __shared__ float shs[8], shq[8];
    __shared__ float sh_mean, sh_rstd;
    __shared__ float s_nud[2];

    int node = blockIdx.x;
    int t = threadIdx.x;
    int lane = t & 31, warp = t >> 5;
    int start = g_off[node];
    int deg   = g_off[node + 1] - start;

    s_xr[t]  = g_xr[(size_t)node * 256 + t];
    s_att[t] = att[t];
    for (int i = t; i < 768; i += 256)
        s_ew[(i % 3) * 256 + (i / 3)] = lin_e_w[i];
    if (t == 0) { s_nud[0] = g_nu[2 * node]; s_nud[1] = g_nu[2 * node + 1]; }
    __syncthreads();

    bool small = (deg <= DEGC);

    // ---- pass 1: logits, warp per edge, chunks of DEGC ----
    for (int c0 = 0; c0 < deg; c0 += DEGC) {
        int cnt = min(DEGC, deg - c0);
        for (int j = t; j < cnt; j += 256) {
            s_src[j] = g_csrc[start + c0 + j];
            s_eid[j] = g_ceid[start + c0 + j];
        }
        __syncthreads();
        for (int j = warp; j < cnt; j += 8) {
            int src = s_src[j];
            int eid = s_eid[j];
            float a0 = s_nud[0] - __ldg(&g_nu[2 * src]);
            float a1 = s_nud[1] - __ldg(&g_nu[2 * src + 1]);
            float a2 = sqrtf(a0 * a0 + a1 * a1);
            if (lane == 0) {
                dout[EA_OFF + (size_t)eid * 3]     = a0;
                dout[EA_OFF + (size_t)eid * 3 + 1] = a1;
                dout[EA_OFF + (size_t)eid * 3 + 2] = a2;
            }
            int f0 = lane * 8;
            const float* xlp = &g_xl[(size_t)src * 256 + f0];
            float4 l0 = *(const float4*)xlp, l1 = *(const float4*)(xlp + 4);
            float4 r0 = *(const float4*)&s_xr[f0],       r1 = *(const float4*)&s_xr[f0 + 4];
            float4 e00 = *(const float4*)&s_ew[f0],       e01 = *(const float4*)&s_ew[f0 + 4];
            float4 e10 = *(const float4*)&s_ew[256 + f0], e11 = *(const float4*)&s_ew[256 + f0 + 4];
            float4 e20 = *(const float4*)&s_ew[512 + f0], e21 = *(const float4*)&s_ew[512 + f0 + 4];
            float4 at0 = *(const float4*)&s_att[f0],      at1 = *(const float4*)&s_att[f0 + 4];
            float xs[8]  = {l0.x + r0.x, l0.y + r0.y, l0.z + r0.z, l0.w + r0.w,
                            l1.x + r1.x, l1.y + r1.y, l1.z + r1.z, l1.w + r1.w};
            float e0a[8] = {e00.x, e00.y, e00.z, e00.w, e01.x, e01.y, e01.z, e01.w};
            float e1a[8] = {e10.x, e10.y, e10.z, e10.w, e11.x, e11.y, e11.z, e11.w};
            float e2a[8] = {e20.x, e20.y, e20.z, e20.w, e21.x, e21.y, e21.z, e21.w};
            float ata[8] = {at0.x, at0.y, at0.z, at0.w, at1.x, at1.y, at1.z, at1.w};
            float acc = 0.0f;
            #pragma unroll
            for (int i = 0; i < 8; i++) {
                float vv = xs[i] + e0a[i] * a0 + e1a[i] * a1 + e2a[i] * a2;
                vv = vv > 0.0f ? vv : 0.2f * vv;
                acc += vv * ata[i];
            }
            acc += __shfl_xor_sync(0xffffffffu, acc, 1);
            acc += __shfl_xor_sync(0xffffffffu, acc, 2);
            acc += __shfl_xor_sync(0xffffffffu, acc, 4);
            if ((lane & 7) == 0) {
                if (small) s_logit[j * 4 + (lane >> 3)] = acc;
                else       g_logits[(size_t)eid * 4 + (lane >> 3)] = acc;
            }
        }
        __syncthreads();
    }

    // ---- softmax over destination neighborhood ----
    int h = t & 3;
    float mx = -1e30f;
    if (small) {
        for (int j = t >> 2; j < deg; j += 64)
            mx = fmaxf(mx, s_logit[j * 4 + h]);
    } else {
        for (int j = t >> 2; j < deg; j += 64) {
            int eid = g_ceid[start + j];
            mx = fmaxf(mx, g_logits[(size_t)eid * 4 + h]);
        }
    }
    mx = fmaxf(mx, __shfl_xor_sync(0xffffffffu, mx, 4));
    mx = fmaxf(mx, __shfl_xor_sync(0xffffffffu, mx, 8));
    mx = fmaxf(mx, __shfl_xor_sync(0xffffffffu, mx, 16));
    if (lane < 4) sh_red[warp * 4 + lane] = mx;
    __syncthreads();
    if (t < 4) {
        float m = sh_red[t];
        #pragma unroll
        for (int wq = 1; wq < 8; wq++) m = fmaxf(m, sh_red[wq * 4 + t]);
        sh_m[t] = m;
    }
    __syncthreads();

    float mh = sh_m[h];
    float sm = 0.0f;
    if (small) {
        for (int j = t >> 2; j < deg; j += 64) {
            float e = expf(s_logit[j * 4 + h] - mh);
            s_logit[j * 4 + h] = e;
            sm += e;
        }
    } else {
        for (int j = t >> 2; j < deg; j += 64) {
            int eid = g_ceid[start + j];
            float e = expf(g_logits[(size_t)eid * 4 + h] - mh);
            g_logits[(size_t)eid * 4 + h] = e;
            sm += e;
        }
    }
    sm += __shfl_xor_sync(0xffffffffu, sm, 4);
    sm += __shfl_xor_sync(0xffffffffu, sm, 8);
    sm += __shfl_xor_sync(0xffffffffu, sm, 16);
    if (lane < 4) sh_red[warp * 4 + lane] = sm;
    __syncthreads();
    if (t < 4) {
        float s = 0.0f;
        #pragma unroll
        for (int wq = 0; wq < 8; wq++) s += sh_red[wq * 4 + t];
        sh_inv[t] = 1.0f / (s + 1e-16f);
    }
    __syncthreads();

    float invh = sh_inv[h];
    if (small) {
        for (int j = t >> 2; j < deg; j += 64) {
            float al = s_logit[j * 4 + h] * invh;
            s_logit[j * 4 + h] = al;
            dout[AL_OFF + (size_t)s_eid[j] * 4 + h] = al;
        }
    } else {
        for (int j = t >> 2; j < deg; j += 64) {
            int eid = g_ceid[start + j];
            float al = g_logits[(size_t)eid * 4 + h] * invh;
            g_logits[(size_t)eid * 4 + h] = al;
            dout[AL_OFF + (size_t)eid * 4 + h] = al;
        }
    }
    __syncthreads();

    // ---- weighted gather-accumulate (thread t <-> feature t) ----
    int hf = t >> 6;
    float acc = 0.0f;
    if (small) {
        int j = 0;
        for (; j + 4 <= deg; j += 4) {
            int s0 = s_src[j], s1 = s_src[j + 1], s2 = s_src[j + 2], s3 = s_src[j + 3];
            float a0 = s_logit[j * 4 + hf],       a1 = s_logit[(j + 1) * 4 + hf];
            float a2 = s_logit[(j + 2) * 4 + hf], a3 = s_logit[(j + 3) * 4 + hf];
            float x0 = __ldg(&g_xl[(size_t)s0 * 256 + t]);
            float x1 = __ldg(&g_xl[(size_t)s1 * 256 + t]);
            float x2 = __ldg(&g_xl[(size_t)s2 * 256 + t]);
            float x3 = __ldg(&g_xl[(size_t)s3 * 256 + t]);
            acc += a0 * x0 + a1 * x1 + a2 * x2 + a3 * x3;
        }
        for (; j < deg; j++)
            acc += s_logit[j * 4 + hf] * __ldg(&g_xl[(size_t)s_src[j] * 256 + t]);
    } else {
        for (int c0 = 0; c0 < deg; c0 += DEGC) {
            int cnt = min(DEGC, deg - c0);
            for (int j = t; j < cnt; j += 256)
                s_src[j] = g_csrc[start + c0 + j];
            for (int i = t; i < cnt * 4; i += 256) {
                int jj = i >> 2, hh = i & 3;
                s_logit[jj * 4 + hh] = g_logits[(size_t)g_ceid[start + c0 + jj] * 4 + hh];
            }
            __syncthreads();
            int j = 0;
            for (; j + 4 <= cnt; j += 4) {
                int s0 = s_src[j], s1 = s_src[j + 1], s2 = s_src[j + 2], s3 = s_src[j + 3];
                float a0 = s_logit[j * 4 + hf],       a1 = s_logit[(j + 1) * 4 + hf];
                float a2 = s_logit[(j + 2) * 4 + hf], a3 = s_logit[(j + 3) * 4 + hf];
                acc += a0 * __ldg(&g_xl[(size_t)s0 * 256 + t])
                     + a1 * __ldg(&g_xl[(size_t)s1 * 256 + t])
                     + a2 * __ldg(&g_xl[(size_t)s2 * 256 + t])
                     + a3 * __ldg(&g_xl[(size_t)s3 * 256 + t]);
            }
            for (; j < cnt; j++)
                acc += s_logit[j * 4 + hf] * __ldg(&g_xl[(size_t)s_src[j] * 256 + t]);
            __syncthreads();
        }
    }

    // ---- epilogue: +conv_b, LayerNorm(256), +identity, silu -> act ----
    float vout = acc + conv_b[t];
    float sv = vout, sq = vout * vout;
    #pragma unroll
    for (int ss = 16; ss; ss >>= 1) {
        sv += __shfl_xor_sync(0xffffffffu, sv, ss);
        sq += __shfl_xor_sync(0xffffffffu, sq, ss);
    }
    if (lane == 0) { shs[warp] = sv; shq[warp] = sq; }
    __syncthreads();
    if (t == 0) {
        float a = 0.0f, b = 0.0f;
        #pragma unroll
        for (int wq = 0; wq < 8; wq++) { a += shs[wq]; b += shq[wq]; }
        float mean = a * (1.0f / 256.0f);
        float var  = b * (1.0f / 256.0f) - mean * mean;
        sh_mean = mean;
        sh_rstd = rsqrtf(var + 1e-5f);
    }
    __syncthreads();
    float y = (vout - sh_mean) * sh_rstd * norm_g[t] + norm_b[t];
    float z = y + g_iden[(size_t)node * 256 + t];
    g_act[(size_t)node * 256 + t] = z / (1.0f + expf(-z));
}

// ---------------- host ----------------
extern "C" void kernel_launch(void* const* d_in, const int* in_sizes, int n_in,
                              void* d_out, int out_size)
{
    const float* x        = (const float*)d_in[0];
    const float* kpts     = (const float*)d_in[1];
    const float* pts3     = (const float*)d_in[2];
    const float* pe_w1    = (const float*)d_in[3];
    const float* pe_b1    = (const float*)d_in[4];
    const float* pe_g1    = (const float*)d_in[5];
    const float* pe_bn1   = (const float*)d_in[6];
    const float* pe_w2    = (const float*)d_in[7];
    const float* pe_b2    = (const float*)d_in[8];
    const float* pe_g2    = (const float*)d_in[9];
    const float* pe_bn2   = (const float*)d_in[10];
    const float* lin_l_w  = (const float*)d_in[11];
    const float* lin_l_b  = (const float*)d_in[12];
    const float* lin_r_w  = (const float*)d_in[13];
    const float* lin_r_b  = (const float*)d_in[14];
    const float* lin_e_w  = (const float*)d_in[15];
    const float* att      = (const float*)d_in[16];
    const float* conv_b   = (const float*)d_in[17];
    const float* norm_g   = (const float*)d_in[18];
    const float* norm_b   = (const float*)d_in[19];
    const float* res_w    = (const float*)d_in[20];
    const float* res_b    = (const float*)d_in[21];
    const float* proj_w   = (const float*)d_in[22];
    const float* proj_b   = (const float*)d_in[23];
    const int*   ei       = (const int*)d_in[24];

    int n = in_sizes[0] / XDIM;          // 50000
    int E = in_sizes[24] / 2;            // 800000
    float* out = (float*)d_out;
    size_t AL_OFF = (size_t)n * 256;
    size_t EA_OFF = AL_OFF + (size_t)E * 4;

    void *p_xcomb, *p_xl, *p_xr, *p_iden, *p_act;
    cudaGetSymbolAddress(&p_xcomb, g_xcomb);
    cudaGetSymbolAddress(&p_xl, g_xl);
    cudaGetSymbolAddress(&p_xr, g_xr);
    cudaGetSymbolAddress(&p_iden, g_iden);
    cudaGetSymbolAddress(&p_act, g_act);

    // 0) zero counters
    zero_counts<<<(n + 256) / 256, 256>>>(n);

    // 1) positional encoder + concat
    node_pre<<<(n * 32 + 255) / 256, 256>>>(x, kpts, pts3,
                                            pe_w1, pe_b1, pe_g1, pe_bn1,
                                            pe_w2, pe_b2, pe_g2, pe_bn2, n);

    // 2) dense transforms
    dim3 gg((n + BM - 1) / BM, 256 / BN);
    gemm256<<<gg, 256>>>((const float*)p_xcomb, lin_l_w, lin_l_b, (float*)p_xl, n);
    gemm256<<<gg, 256>>>((const float*)p_xcomb, lin_r_w, lin_r_b, (float*)p_xr, n);
    gemm256<<<gg, 256>>>((const float*)p_xcomb, res_w,   res_b,   (float*)p_iden, n);

    // 3) CSR by destination
    count_deg<<<(E + 255) / 256, 256>>>(ei, E);
    scan_offsets<<<1, 1024>>>(n);
    fill_csr<<<(E + 255) / 256, 256>>>(ei, E);

    // 4) fused: edge attrs + logits + softmax + aggregate + epilogue
    fused_node<<<n, 256>>>(lin_e_w, att, conv_b, norm_g, norm_b,
                           out, AL_OFF, EA_OFF, n);

    // 5) final projection -> out
    gemm256<<<gg, 256>>>((const float*)p_act, proj_w, proj_b, out, n);
}

// round 14
// speedup vs baseline: 2.6548x; 1.4247x over previous
#include <cuda_runtime.h>
#include <cuda_bf16.h>
#include <cstdint>
#include <cstddef>

// ---------------- problem constants ----------------
#define NMAX 50176
#define EMAX 800000
#define XDIM 192
#define DEGC 512

// ---------------- device scratch (static, no allocation) ----------------
__device__ __nv_bfloat16 g_xc_h [(size_t)NMAX * 256];
__device__ __nv_bfloat16 g_xc_l [(size_t)NMAX * 256];
__device__ __nv_bfloat16 g_act_h[(size_t)NMAX * 256];
__device__ __nv_bfloat16 g_act_l[(size_t)NMAX * 256];
__device__ __nv_bfloat16 g_wh[4 * 65536];
__device__ __nv_bfloat16 g_wl[4 * 65536];
__device__ float g_xl   [(size_t)NMAX * 256];
__device__ float g_xr   [(size_t)NMAX * 256];
__device__ float g_iden [(size_t)NMAX * 256];
__device__ float g_nu   [(size_t)NMAX * 2];
__device__ float g_logits[(size_t)EMAX * 4];
__device__ int   g_deg [NMAX + 1];
__device__ int   g_off [NMAX + 1];
__device__ int   g_fill[NMAX + 1];
__device__ int   g_ceid[EMAX];
__device__ int   g_csrc[EMAX];

// ---------------- helpers ----------------
__device__ __forceinline__ float wredsum(float v) {
    #pragma unroll
    for (int s = 16; s; s >>= 1) v += __shfl_xor_sync(0xffffffffu, v, s);
    return v;
}
__device__ __forceinline__ void store_split(__nv_bfloat16* H, __nv_bfloat16* L,
                                            size_t idx, float v) {
    __nv_bfloat16 h = __float2bfloat16(v);
    H[idx] = h;
    L[idx] = __float2bfloat16(v - __bfloat162float(h));
}
__device__ __forceinline__ void ldm4(uint32_t* r, uint32_t addr) {
    asm volatile("ldmatrix.sync.aligned.m8n8.x4.shared.b16 {%0,%1,%2,%3}, [%4];"
        : "=r"(r[0]), "=r"(r[1]), "=r"(r[2]), "=r"(r[3]) : "r"(addr));
}
__device__ __forceinline__ void mma_bf16(float* c, const uint32_t* a, const uint32_t* b) {
    asm volatile("mma.sync.aligned.m16n8k16.row.col.f32.bf16.bf16.f32 "
        "{%0,%1,%2,%3}, {%4,%5,%6,%7}, {%8,%9}, {%0,%1,%2,%3};"
        : "+f"(c[0]), "+f"(c[1]), "+f"(c[2]), "+f"(c[3])
        : "r"(a[0]), "r"(a[1]), "r"(a[2]), "r"(a[3]), "r"(b[0]), "r"(b[1]));
}
__device__ __forceinline__ void cpa16(uint32_t dst, const void* src) {
    asm volatile("cp.async.cg.shared.global [%0], [%1], 16;" :: "r"(dst), "l"(src));
}

// ---------------- K0: zero CSR counters ----------------
__global__ void zero_counts(int n) {
    int i = blockIdx.x * blockDim.x + threadIdx.x;
    if (i <= n) { g_deg[i] = 0; g_fill[i] = 0; }
}

// ---------------- K-1: weight hi/lo conversion (4 matrices of 256x256) ------
__global__ void conv_w(const float* __restrict__ w0, const float* __restrict__ w1,
                       const float* __restrict__ w2, const float* __restrict__ w3)
{
    int i = blockIdx.x * 256 + threadIdx.x;   // 0..65535
    int m = blockIdx.y;
    const float* src = (m == 0) ? w0 : (m == 1) ? w1 : (m == 2) ? w2 : w3;
    float v = src[i];
    store_split(g_wh, g_wl, (size_t)m * 65536 + i, v);
}

// ---------------- K1: positional encoder + concat (one warp / node) ----------
__global__ __launch_bounds__(256) void node_pre(
        const float* __restrict__ x, const float* __restrict__ kpts,
        const float* __restrict__ pts3,
        const float* __restrict__ pe_w1, const float* __restrict__ pe_b1,
        const float* __restrict__ pe_g1, const float* __restrict__ pe_bn1,
        const float* __restrict__ pe_w2, const float* __restrict__ pe_b2,
        const float* __restrict__ pe_g2, const float* __restrict__ pe_bn2,
        int n)
{
    __shared__ float s_w2t[32][65];
    int t = threadIdx.x;
    for (int i = t; i < 2048; i += 256) {
        int out = i >> 5, k = i & 31;
        s_w2t[k][out] = pe_w2[i];
    }
    __syncthreads();

    int node = (blockIdx.x * 256 + t) >> 5;
    int lane = t & 31;
    if (node >= n) return;

    float u = kpts[2 * node]     * (1.0f / 1216.0f);
    float v = kpts[2 * node + 1] * (1.0f / 352.0f);
    float d = pts3[3 * node + 2];
    d = fminf(fmaxf(d, 0.1f), 100.0f);
    if (lane == 0) { g_nu[2 * node] = u; g_nu[2 * node + 1] = v; }

    float h1 = pe_b1[lane] + pe_w1[lane * 3] * u + pe_w1[lane * 3 + 1] * v + pe_w1[lane * 3 + 2] * d;
    float m  = wredsum(h1) * (1.0f / 32.0f);
    float c  = h1 - m;
    float vr = wredsum(c * c) * (1.0f / 32.0f);
    float y  = c * rsqrtf(vr + 1e-5f) * pe_g1[lane] + pe_bn1[lane];
    y = y / (1.0f + expf(-y));

    float o0 = pe_b2[lane], o1 = pe_b2[lane + 32];
    #pragma unroll
    for (int k = 0; k < 32; k++) {
        float hk = __shfl_sync(0xffffffffu, y, k);
        o0 += s_w2t[k][lane]      * hk;
        o1 += s_w2t[k][lane + 32] * hk;
    }
    float m2 = wredsum(o0 + o1) * (1.0f / 64.0f);
    float c0 = o0 - m2, c1 = o1 - m2;
    float v2 = wredsum(c0 * c0 + c1 * c1) * (1.0f / 64.0f);
    float r  = rsqrtf(v2 + 1e-5f);
    float p0 = c0 * r * pe_g2[lane]      + pe_bn2[lane];
    float p1 = c1 * r * pe_g2[lane + 32] + pe_bn2[lane + 32];

    size_t base = (size_t)node * 256;
    store_split(g_xc_h, g_xc_l, base + 192 + lane, p0);
    store_split(g_xc_h, g_xc_l, base + 224 + lane, p1);
    #pragma unroll
    for (int i = lane; i < XDIM; i += 32)
        store_split(g_xc_h, g_xc_l, base + i, x[(size_t)node * XDIM + i]);
}

// ---------------- K2: bf16-split tensor-core GEMM core ---------------------
// C[M,256] = (Ah+Al)[M,256] @ (Wh+Wl)^T[256,256] + bias  (drops Al*Wl term)
// block 128(M) x 128(N), 8 warps (2m x 4n), warp tile 64x32, BK=32, cp.async x2
#define RS   40                    // smem row stride in bf16 (32 + 8 pad)
#define MAT  (128 * RS)
#define STG  (4 * MAT)
#define GSMEM (2 * STG * 2)

__device__ __forceinline__ void tc_gemm_core(
        const __nv_bfloat16* __restrict__ Ah, const __nv_bfloat16* __restrict__ Al,
        const __nv_bfloat16* __restrict__ Wh, const __nv_bfloat16* __restrict__ Wl,
        const float* __restrict__ bias, float* __restrict__ C, int M,
        int m0, int f0, __nv_bfloat16* smem)
{
    uint32_t sbase = (uint32_t)__cvta_generic_to_shared(smem);

    int tid = threadIdx.x;
    int w = tid >> 5, l = tid & 31;
    int wm = w & 1, wn = w >> 1;

    int a_row = l & 15;
    int a_kof = (l >> 4) << 3;
    int b_row = (l & 7) + ((l >> 4) << 3);
    int b_kof = ((l >> 3) & 1) << 3;

    float acc[4][4][4];
    #pragma unroll
    for (int i = 0; i < 4; i++)
        #pragma unroll
        for (int j = 0; j < 4; j++)
            #pragma unroll
            for (int k = 0; k < 4; k++) acc[i][j][k] = 0.0f;

    auto load_stage = [&](int buf, int kt) {
        int kblk = kt * 32;
        #pragma unroll
        for (int i = 0; i < 2; i++) {
            int chunk = tid + i * 256;
            int row = chunk >> 2, sub = chunk & 3;
            uint32_t so = sbase + (uint32_t)(buf * STG + row * RS + sub * 8) * 2;
            cpa16(so,               Ah + (size_t)(m0 + row) * 256 + kblk + sub * 8);
            cpa16(so + MAT * 2,     Al + (size_t)(m0 + row) * 256 + kblk + sub * 8);
            cpa16(so + 2 * MAT * 2, Wh + (size_t)(f0 + row) * 256 + kblk + sub * 8);
            cpa16(so + 3 * MAT * 2, Wl + (size_t)(f0 + row) * 256 + kblk + sub * 8);
        }
    };

    load_stage(0, 0);
    asm volatile("cp.async.commit_group;");

    #pragma unroll 1
    for (int kt = 0; kt < 8; kt++) {
        if (kt < 7) {
            load_stage((kt + 1) & 1, kt + 1);
            asm volatile("cp.async.commit_group;");
            asm volatile("cp.async.wait_group 1;");
        } else {
            asm volatile("cp.async.wait_group 0;");
        }
        __syncthreads();

        int buf = kt & 1;
        uint32_t sA_h = sbase + (uint32_t)(buf * STG) * 2;
        uint32_t sA_l = sA_h + MAT * 2;
        uint32_t sW_h = sA_h + 2 * MAT * 2;
        uint32_t sW_l = sA_h + 3 * MAT * 2;

        #pragma unroll
        for (int kk = 0; kk < 32; kk += 16) {
            uint32_t bh[2][4], bl[2][4];
            #pragma unroll
            for (int g2 = 0; g2 < 2; g2++) {
                uint32_t boff = (uint32_t)((wn * 32 + g2 * 16 + b_row) * RS + kk + b_kof) * 2;
                ldm4(bh[g2], sW_h + boff);
                ldm4(bl[g2], sW_l + boff);
            }
            #pragma unroll
            for (int mt = 0; mt < 4; mt++) {
                uint32_t aoff = (uint32_t)((wm * 64 + mt * 16 + a_row) * RS + kk + a_kof) * 2;
                uint32_t ah[4], al[4];
                ldm4(ah, sA_h + aoff);
                ldm4(al, sA_l + aoff);
                #pragma unroll
                for (int nt = 0; nt < 4; nt++) {
                    const uint32_t* BH = &bh[nt >> 1][(nt & 1) * 2];
                    const uint32_t* BL = &bl[nt >> 1][(nt & 1) * 2];
                    mma_bf16(acc[mt][nt], ah, BH);
                    mma_bf16(acc[mt][nt], ah, BL);
                    mma_bf16(acc[mt][nt], al, BH);
                }
            }
        }
        __syncthreads();
    }

    #pragma unroll
    for (int mt = 0; mt < 4; mt++) {
        #pragma unroll
        for (int nt = 0; nt < 4; nt++) {
            int row0 = m0 + wm * 64 + mt * 16 + (l >> 2);
            int col  = f0 + wn * 32 + nt * 8 + (l & 3) * 2;
            float b0v = bias[col], b1v = bias[col + 1];
            if (row0 < M) {
                float2 v = make_float2(acc[mt][nt][0] + b0v, acc[mt][nt][1] + b1v);
                *(float2*)&C[(size_t)row0 * 256 + col] = v;
            }
            if (row0 + 8 < M) {
                float2 v = make_float2(acc[mt][nt][2] + b0v, acc[mt][nt][3] + b1v);
                *(float2*)&C[(size_t)(row0 + 8) * 256 + col] = v;
            }
        }
    }
}

// merged 3-GEMM launch: blockIdx.y in [0,6) -> (matrix 0..2, N-half 0..1)
__global__ __launch_bounds__(256) void tc_gemm3(
        const __nv_bfloat16* __restrict__ Ah, const __nv_bfloat16* __restrict__ Al,
        const float* __restrict__ b0, const float* __restrict__ b1,
        const float* __restrict__ b2,
        float* __restrict__ C0, float* __restrict__ C1, float* __restrict__ C2,
        int M)
{
    extern __shared__ __align__(16) __nv_bfloat16 smem[];
    int mi = blockIdx.y >> 1;
    int f0 = (blockIdx.y & 1) * 128;
    const float* bias = (mi == 0) ? b0 : (mi == 1) ? b1 : b2;
    float* C = (mi == 0) ? C0 : (mi == 1) ? C1 : C2;
    tc_gemm_core(Ah, Al, g_wh + (size_t)mi * 65536, g_wl + (size_t)mi * 65536,
                 bias, C, M, blockIdx.x * 128, f0, smem);
}

// single GEMM (projection)
__global__ __launch_bounds__(256) void tc_gemm1(
        const __nv_bfloat16* __restrict__ Ah, const __nv_bfloat16* __restrict__ Al,
        const float* __restrict__ bias, float* __restrict__ C, int M)
{
    extern __shared__ __align__(16) __nv_bfloat16 smem[];
    tc_gemm_core(Ah, Al, g_wh + 3 * 65536, g_wl + 3 * 65536,
                 bias, C, M, blockIdx.x * 128, blockIdx.y * 128, smem);
}

// ---------------- K3: CSR build ----------------
__global__ void count_deg(const int* __restrict__ ei, int E) {
    int i = blockIdx.x * blockDim.x + threadIdx.x;
    if (i < E) atomicAdd(&g_deg[ei[E + i]], 1);
}

__global__ void scan_offsets(int n) {
    __shared__ int wsum[32];
    __shared__ int carry;
    int t = threadIdx.x, lane = t & 31, w = t >> 5;
    if (t == 0) { carry = 0; g_off[0] = 0; }
    __syncthreads();
    for (int base = 0; base < n; base += 1024) {
        int i = base + t;
        int v = (i < n) ? g_deg[i] : 0;
        int sc = v;
        #pragma unroll
        for (int s = 1; s < 32; s <<= 1) {
            int xv = __shfl_up_sync(0xffffffffu, sc, s);
            if (lane >= s) sc += xv;
        }
        if (lane == 31) wsum[w] = sc;
        __syncthreads();
        if (w == 0) {
            int ws = wsum[lane];
            #pragma unroll
            for (int s = 1; s < 32; s <<= 1) {
                int xv = __shfl_up_sync(0xffffffffu, ws, s);
                if (lane >= s) ws += xv;
            }
            wsum[lane] = ws;
        }
        __syncthreads();
        int add = carry + (w ? wsum[w - 1] : 0);
        if (i < n) g_off[i + 1] = add + sc;
        int total = wsum[31];
        __syncthreads();
        if (t == 0) carry += total;
        __syncthreads();
    }
}

__global__ void fill_csr(const int* __restrict__ ei, int E) {
    int i = blockIdx.x * blockDim.x + threadIdx.x;
    if (i < E) {
        int d = ei[E + i];
        int p = g_off[d] + atomicAdd(&g_fill[d], 1);
        g_ceid[p] = i;
        g_csrc[p] = ei[i];
    }
}

// ---------------- K4: FUSED per-node kernel -------------------------------
__global__ __launch_bounds__(256) void fused_node(
        const float* __restrict__ lin_e_w, const float* __restrict__ att,
        const float* __restrict__ conv_b, const float* __restrict__ norm_g,
        const float* __restrict__ norm_b, float* __restrict__ dout,
        size_t AL_OFF, size_t EA_OFF, int n)
{
    __shared__ __align__(16) float s_xr[256];
    __shared__ __align__(16) float s_ew[768];
    __shared__ __align__(16) float s_att[256];
    __shared__ int   s_src[DEGC];
    __shared__ int   s_eid[DEGC];
    __shared__ __align__(16) float s_logit[DEGC * 4];
    __shared__ float sh_red[32], sh_m[4], sh_inv[4];
    __shared__ float shs[8], shq[8];
    __shared__ float sh_mean, sh_rstd;
    __shared__ float s_nud[2];

    int node = blockIdx.x;
    int t = threadIdx.x;
    int lane = t & 31, warp = t >> 5;
    int start = g_off[node];
    int deg   = g_off[node + 1] - start;

    s_xr[t]  = g_xr[(size_t)node * 256 + t];
    s_att[t] = att[t];
    for (int i = t; i < 768; i += 256)
        s_ew[(i % 3) * 256 + (i / 3)] = lin_e_w[i];
    if (t == 0) { s_nud[0] = g_nu[2 * node]; s_nud[1] = g_nu[2 * node + 1]; }
    __syncthreads();

    bool small = (deg <= DEGC);

    // ---- pass 1: logits, warp per edge ----
    for (int c0 = 0; c0 < deg; c0 += DEGC) {
        int cnt = min(DEGC, deg - c0);
        for (int j = t; j < cnt; j += 256) {
            s_src[j] = g_csrc[start + c0 + j];
            s_eid[j] = g_ceid[start + c0 + j];
        }
        __syncthreads();
        for (int j = warp; j < cnt; j += 8) {
            int src = s_src[j];
            int eid = s_eid[j];
            float a0 = s_nud[0] - __ldg(&g_nu[2 * src]);
            float a1 = s_nud[1] - __ldg(&g_nu[2 * src + 1]);
            float a2 = sqrtf(a0 * a0 + a1 * a1);
            if (lane == 0) {
                dout[EA_OFF + (size_t)eid * 3]     = a0;
                dout[EA_OFF + (size_t)eid * 3 + 1] = a1;
                dout[EA_OFF + (size_t)eid * 3 + 2] = a2;
            }
            int f0 = lane * 8;
            const float* xlp = &g_xl[(size_t)src * 256 + f0];
            float4 l0 = *(const float4*)xlp, l1 = *(const float4*)(xlp + 4);
            float4 r0 = *(const float4*)&s_xr[f0],       r1 = *(const float4*)&s_xr[f0 + 4];
            float4 e00 = *(const float4*)&s_ew[f0],       e01 = *(const float4*)&s_ew[f0 + 4];
            float4 e10 = *(const float4*)&s_ew[256 + f0], e11 = *(const float4*)&s_ew[256 + f0 + 4];
            float4 e20 = *(const float4*)&s_ew[512 + f0], e21 = *(const float4*)&s_ew[512 + f0 + 4];
            float4 at0 = *(const float4*)&s_att[f0],      at1 = *(const float4*)&s_att[f0 + 4];
            float xs[8]  = {l0.x + r0.x, l0.y + r0.y, l0.z + r0.z, l0.w + r0.w,
                            l1.x + r1.x, l1.y + r1.y, l1.z + r1.z, l1.w + r1.w};
            float e0a[8] = {e00.x, e00.y, e00.z, e00.w, e01.x, e01.y, e01.z, e01.w};
            float e1a[8] = {e10.x, e10.y, e10.z, e10.w, e11.x, e11.y, e11.z, e11.w};
            float e2a[8] = {e20.x, e20.y, e20.z, e20.w, e21.x, e21.y, e21.z, e21.w};
            float ata[8] = {at0.x, at0.y, at0.z, at0.w, at1.x, at1.y, at1.z, at1.w};
            float acc = 0.0f;
            #pragma unroll
            for (int i = 0; i < 8; i++) {
                float vv = xs[i] + e0a[i] * a0 + e1a[i] * a1 + e2a[i] * a2;
                vv = vv > 0.0f ? vv : 0.2f * vv;
                acc += vv * ata[i];
            }
            acc += __shfl_xor_sync(0xffffffffu, acc, 1);
            acc += __shfl_xor_sync(0xffffffffu, acc, 2);
            acc += __shfl_xor_sync(0xffffffffu, acc, 4);
            if ((lane & 7) == 0) {
                if (small) s_logit[j * 4 + (lane >> 3)] = acc;
                else       g_logits[(size_t)eid * 4 + (lane >> 3)] = acc;
            }
        }
        __syncthreads();
    }

    // ---- softmax ----
    int h = t & 3;
    float mx = -1e30f;
    if (small) {
        for (int j = t >> 2; j < deg; j += 64)
            mx = fmaxf(mx, s_logit[j * 4 + h]);
    } else {
        for (int j = t >> 2; j < deg; j += 64) {
            int eid = g_ceid[start + j];
            mx = fmaxf(mx, g_logits[(size_t)eid * 4 + h]);
        }
    }
    mx = fmaxf(mx, __shfl_xor_sync(0xffffffffu, mx, 4));
    mx = fmaxf(mx, __shfl_xor_sync(0xffffffffu, mx, 8));
    mx = fmaxf(mx, __shfl_xor_sync(0xffffffffu, mx, 16));
    if (lane < 4) sh_red[warp * 4 + lane] = mx;
    __syncthreads();
    if (t < 4) {
        float m = sh_red[t];
        #pragma unroll
        for (int wq = 1; wq < 8; wq++) m = fmaxf(m, sh_red[wq * 4 + t]);
        sh_m[t] = m;
    }
    __syncthreads();

    float mh = sh_m[h];
    float sm = 0.0f;
    if (small) {
        for (int j = t >> 2; j < deg; j += 64) {
            float e = expf(s_logit[j * 4 + h] - mh);
            s_logit[j * 4 + h] = e;
            sm += e;
        }
    } else {
        for (int j = t >> 2; j < deg; j += 64) {
            int eid = g_ceid[start + j];
            float e = expf(g_logits[(size_t)eid * 4 + h] - mh);
            g_logits[(size_t)eid * 4 + h] = e;
            sm += e;
        }
    }
    sm += __shfl_xor_sync(0xffffffffu, sm, 4);
    sm += __shfl_xor_sync(0xffffffffu, sm, 8);
    sm += __shfl_xor_sync(0xffffffffu, sm, 16);
    if (lane < 4) sh_red[warp * 4 + lane] = sm;
    __syncthreads();
    if (t < 4) {
        float s = 0.0f;
        #pragma unroll
        for (int wq = 0; wq < 8; wq++) s += sh_red[wq * 4 + t];
        sh_inv[t] = 1.0f / (s + 1e-16f);
    }
    __syncthreads();

    float invh = sh_inv[h];
    if (small) {
        for (int j = t >> 2; j < deg; j += 64) {
            float al = s_logit[j * 4 + h] * invh;
            s_logit[j * 4 + h] = al;
            dout[AL_OFF + (size_t)s_eid[j] * 4 + h] = al;
        }
    } else {
        for (int j = t >> 2; j < deg; j += 64) {
            int eid = g_ceid[start + j];
            float al = g_logits[(size_t)eid * 4 + h] * invh;
            g_logits[(size_t)eid * 4 + h] = al;
            dout[AL_OFF + (size_t)eid * 4 + h] = al;
        }
    }
    __syncthreads();

    // ---- weighted gather-accumulate ----
    int hf = t >> 6;
    float acc = 0.0f;
    if (small) {
        int j = 0;
        for (; j + 4 <= deg; j += 4) {
            int s0 = s_src[j], s1 = s_src[j + 1], s2 = s_src[j + 2], s3 = s_src[j + 3];
            float a0 = s_logit[j * 4 + hf],       a1 = s_logit[(j + 1) * 4 + hf];
            float a2 = s_logit[(j + 2) * 4 + hf], a3 = s_logit[(j + 3) * 4 + hf];
            acc += a0 * __ldg(&g_xl[(size_t)s0 * 256 + t])
                 + a1 * __ldg(&g_xl[(size_t)s1 * 256 + t])
                 + a2 * __ldg(&g_xl[(size_t)s2 * 256 + t])
                 + a3 * __ldg(&g_xl[(size_t)s3 * 256 + t]);
        }
        for (; j < deg; j++)
            acc += s_logit[j * 4 + hf] * __ldg(&g_xl[(size_t)s_src[j] * 256 + t]);
    } else {
        for (int c0 = 0; c0 < deg; c0 += DEGC) {
            int cnt = min(DEGC, deg - c0);
            for (int j = t; j < cnt; j += 256)
                s_src[j] = g_csrc[start + c0 + j];
            for (int i = t; i < cnt * 4; i += 256) {
                int jj = i >> 2, hh = i & 3;
                s_logit[jj * 4 + hh] = g_logits[(size_t)g_ceid[start + c0 + jj] * 4 + hh];
            }
            __syncthreads();
            int j = 0;
            for (; j + 4 <= cnt; j += 4) {
                int s0 = s_src[j], s1 = s_src[j + 1], s2 = s_src[j + 2], s3 = s_src[j + 3];
                float a0 = s_logit[j * 4 + hf],       a1 = s_logit[(j + 1) * 4 + hf];
                float a2 = s_logit[(j + 2) * 4 + hf], a3 = s_logit[(j + 3) * 4 + hf];
                acc += a0 * __ldg(&g_xl[(size_t)s0 * 256 + t])
                     + a1 * __ldg(&g_xl[(size_t)s1 * 256 + t])
                     + a2 * __ldg(&g_xl[(size_t)s2 * 256 + t])
                     + a3 * __ldg(&g_xl[(size_t)s3 * 256 + t]);
            }
            for (; j < cnt; j++)
                acc += s_logit[j * 4 + hf] * __ldg(&g_xl[(size_t)s_src[j] * 256 + t]);
            __syncthreads();
        }
    }

    // ---- epilogue ----
    float vout = acc + conv_b[t];
    float sv = vout, sq = vout * vout;
    #pragma unroll
    for (int ss = 16; ss; ss >>= 1) {
        sv += __shfl_xor_sync(0xffffffffu, sv, ss);
        sq += __shfl_xor_sync(0xffffffffu, sq, ss);
    }
    if (lane == 0) { shs[warp] = sv; shq[warp] = sq; }
    __syncthreads();
    if (t == 0) {
        float a = 0.0f, b = 0.0f;
        #pragma unroll
        for (int wq = 0; wq < 8; wq++) { a += shs[wq]; b += shq[wq]; }
        float mean = a * (1.0f / 256.0f);
        float var  = b * (1.0f / 256.0f) - mean * mean;
        sh_mean = mean;
        sh_rstd = rsqrtf(var + 1e-5f);
    }
    __syncthreads();
    float y = (vout - sh_mean) * sh_rstd * norm_g[t] + norm_b[t];
    float z = y + g_iden[(size_t)node * 256 + t];
    float act = z / (1.0f + expf(-z));
    store_split(g_act_h, g_act_l, (size_t)node * 256 + t, act);
}

// ---------------- host ----------------
extern "C" void kernel_launch(void* const* d_in, const int* in_sizes, int n_in,
                              void* d_out, int out_size)
{
    const float* x        = (const float*)d_in[0];
    const float* kpts     = (const float*)d_in[1];
    const float* pts3     = (const float*)d_in[2];
    const float* pe_w1    = (const float*)d_in[3];
    const float* pe_b1    = (const float*)d_in[4];
    const float* pe_g1    = (const float*)d_in[5];
    const float* pe_bn1   = (const float*)d_in[6];
    const float* pe_w2    = (const float*)d_in[7];
    const float* pe_b2    = (const float*)d_in[8];
    const float* pe_g2    = (const float*)d_in[9];
    const float* pe_bn2   = (const float*)d_in[10];
    const float* lin_l_w  = (const float*)d_in[11];
    const float* lin_l_b  = (const float*)d_in[12];
    const float* lin_r_w  = (const float*)d_in[13];
    const float* lin_r_b  = (const float*)d_in[14];
    const float* lin_e_w  = (const float*)d_in[15];
    const float* att      = (const float*)d_in[16];
    const float* conv_b   = (const float*)d_in[17];
    const float* norm_g   = (const float*)d_in[18];
    const float* norm_b   = (const float*)d_in[19];
    const float* res_w    = (const float*)d_in[20];
    const float* res_b    = (const float*)d_in[21];
    const float* proj_w   = (const float*)d_in[22];
    const float* proj_b   = (const float*)d_in[23];
    const int*   ei       = (const int*)d_in[24];

    int n = in_sizes[0] / XDIM;          // 50000
    int E = in_sizes[24] / 2;            // 800000
    float* out = (float*)d_out;
    size_t AL_OFF = (size_t)n * 256;
    size_t EA_OFF = AL_OFF + (size_t)E * 4;

    void *p_xch, *p_xcl, *p_acth, *p_actl, *p_xl, *p_xr, *p_iden;
    cudaGetSymbolAddress(&p_xch,  g_xc_h);
    cudaGetSymbolAddress(&p_xcl,  g_xc_l);
    cudaGetSymbolAddress(&p_acth, g_act_h);
    cudaGetSymbolAddress(&p_actl, g_act_l);
    cudaGetSymbolAddress(&p_xl,   g_xl);
    cudaGetSymbolAddress(&p_xr,   g_xr);
    cudaGetSymbolAddress(&p_iden, g_iden);

    cudaFuncSetAttribute(tc_gemm3, cudaFuncAttributeMaxDynamicSharedMemorySize, GSMEM);
    cudaFuncSetAttribute(tc_gemm1, cudaFuncAttributeMaxDynamicSharedMemorySize, GSMEM);

    // 0) zero counters + weight conversion
    zero_counts<<<(n + 256) / 256, 256>>>(n);
    conv_w<<<dim3(256, 4), 256>>>(lin_l_w, lin_r_w, res_w, proj_w);

    // 1) positional encoder + concat (writes xcomb hi/lo)
    node_pre<<<(n * 32 + 255) / 256, 256>>>(x, kpts, pts3,
                                            pe_w1, pe_b1, pe_g1, pe_bn1,
                                            pe_w2, pe_b2, pe_g2, pe_bn2, n);

    // 2) dense transforms on tensor cores (3 GEMMs merged in one launch)
    dim3 gg3((n + 127) / 128, 6);
    tc_gemm3<<<gg3, 256, GSMEM>>>((const __nv_bfloat16*)p_xch, (const __nv_bfloat16*)p_xcl,
                                  lin_l_b, lin_r_b, res_b,
                                  (float*)p_xl, (float*)p_xr, (float*)p_iden, n);

    // 3) CSR by destination
    count_deg<<<(E + 255) / 256, 256>>>(ei, E);
    scan_offsets<<<1, 1024>>>(n);
    fill_csr<<<(E + 255) / 256, 256>>>(ei, E);

    // 4) fused: edge attrs + logits + softmax + aggregate + epilogue
    fused_node<<<n, 256>>>(lin_e_w, att, conv_b, norm_g, norm_b,
                           out, AL_OFF, EA_OFF, n);

    // 5) final projection -> out
    dim3 gg1((n + 127) / 128, 2);
    tc_gemm1<<<gg1, 256, GSMEM>>>((const __nv_bfloat16*)p_acth, (const __nv_bfloat16*)p_actl,
                                  proj_b, out, n);
}

// round 17
// speedup vs baseline: 2.8060x; 1.0570x over previous
#include <cuda_runtime.h>
#include <cuda_bf16.h>
#include <cstdint>
#include <cstddef>

// ---------------- problem constants ----------------
#define NMAX 50176
#define EMAX 800000
#define XDIM 192
#define DEGC 128

// ---------------- device scratch (static, no allocation) ----------------
__device__ __nv_bfloat16 g_xc_h [(size_t)NMAX * 256];
__device__ __nv_bfloat16 g_xc_l [(size_t)NMAX * 256];
__device__ __nv_bfloat16 g_act_h[(size_t)NMAX * 256];
__device__ __nv_bfloat16 g_act_l[(size_t)NMAX * 256];
__device__ __nv_bfloat16 g_wh[4 * 65536];
__device__ __nv_bfloat16 g_wl[4 * 65536];
__device__ float g_xl   [(size_t)NMAX * 256];
__device__ float g_xr   [(size_t)NMAX * 256];
__device__ float g_iden [(size_t)NMAX * 256];
__device__ float g_nu   [(size_t)NMAX * 2];
__device__ float g_logits[(size_t)EMAX * 4];   // deg>DEGC fallback only
__device__ int   g_deg [NMAX + 1];
__device__ int   g_off [NMAX + 1];
__device__ int   g_fill[NMAX + 1];
__device__ int   g_ceid[EMAX];
__device__ int   g_csrc[EMAX];

// ---------------- helpers ----------------
__device__ __forceinline__ float wredsum(float v) {
    #pragma unroll
    for (int s = 16; s; s >>= 1) v += __shfl_xor_sync(0xffffffffu, v, s);
    return v;
}
__device__ __forceinline__ void store_split(__nv_bfloat16* H, __nv_bfloat16* L,
                                            size_t idx, float v) {
    __nv_bfloat16 h = __float2bfloat16(v);
    H[idx] = h;
    L[idx] = __float2bfloat16(v - __bfloat162float(h));
}
__device__ __forceinline__ void ldm4(uint32_t* r, uint32_t addr) {
    asm volatile("ldmatrix.sync.aligned.m8n8.x4.shared.b16 {%0,%1,%2,%3}, [%4];"
        : "=r"(r[0]), "=r"(r[1]), "=r"(r[2]), "=r"(r[3]) : "r"(addr));
}
__device__ __forceinline__ void mma_bf16(float* c, const uint32_t* a, const uint32_t* b) {
    asm volatile("mma.sync.aligned.m16n8k16.row.col.f32.bf16.bf16.f32 "
        "{%0,%1,%2,%3}, {%4,%5,%6,%7}, {%8,%9}, {%0,%1,%2,%3};"
        : "+f"(c[0]), "+f"(c[1]), "+f"(c[2]), "+f"(c[3])
        : "r"(a[0]), "r"(a[1]), "r"(a[2]), "r"(a[3]), "r"(b[0]), "r"(b[1]));
}
__device__ __forceinline__ void cpa16(uint32_t dst, const void* src) {
    asm volatile("cp.async.cg.shared.global [%0], [%1], 16;" :: "r"(dst), "l"(src));
}

// ---------------- K0: zero CSR counters ----------------
__global__ void zero_counts(int n) {
    int i = blockIdx.x * blockDim.x + threadIdx.x;
    if (i <= n) { g_deg[i] = 0; g_fill[i] = 0; }
}

// ---------------- K-1: weight hi/lo conversion ----------------
__global__ void conv_w(const float* __restrict__ w0, const float* __restrict__ w1,
                       const float* __restrict__ w2, const float* __restrict__ w3)
{
    int i = blockIdx.x * 256 + threadIdx.x;
    int m = blockIdx.y;
    const float* src = (m == 0) ? w0 : (m == 1) ? w1 : (m == 2) ? w2 : w3;
    store_split(g_wh, g_wl, (size_t)m * 65536 + i, src[i]);
}

// ---------------- K1: positional encoder + concat (one warp / node) ----------
__global__ __launch_bounds__(256) void node_pre(
        const float* __restrict__ x, const float* __restrict__ kpts,
        const float* __restrict__ pts3,
        const float* __restrict__ pe_w1, const float* __restrict__ pe_b1,
        const float* __restrict__ pe_g1, const float* __restrict__ pe_bn1,
        const float* __restrict__ pe_w2, const float* __restrict__ pe_b2,
        const float* __restrict__ pe_g2, const float* __restrict__ pe_bn2,
        int n)
{
    __shared__ float s_w2t[32][65];
    int t = threadIdx.x;
    for (int i = t; i < 2048; i += 256) {
        int out = i >> 5, k = i & 31;
        s_w2t[k][out] = pe_w2[i];
    }
    __syncthreads();

    int node = (blockIdx.x * 256 + t) >> 5;
    int lane = t & 31;
    if (node >= n) return;

    float u = kpts[2 * node]     * (1.0f / 1216.0f);
    float v = kpts[2 * node + 1] * (1.0f / 352.0f);
    float d = pts3[3 * node + 2];
    d = fminf(fmaxf(d, 0.1f), 100.0f);
    if (lane == 0) { g_nu[2 * node] = u; g_nu[2 * node + 1] = v; }

    float h1 = pe_b1[lane] + pe_w1[lane * 3] * u + pe_w1[lane * 3 + 1] * v + pe_w1[lane * 3 + 2] * d;
    float m  = wredsum(h1) * (1.0f / 32.0f);
    float c  = h1 - m;
    float vr = wredsum(c * c) * (1.0f / 32.0f);
    float y  = c * rsqrtf(vr + 1e-5f) * pe_g1[lane] + pe_bn1[lane];
    y = y / (1.0f + expf(-y));

    float o0 = pe_b2[lane], o1 = pe_b2[lane + 32];
    #pragma unroll
    for (int k = 0; k < 32; k++) {
        float hk = __shfl_sync(0xffffffffu, y, k);
        o0 += s_w2t[k][lane]      * hk;
        o1 += s_w2t[k][lane + 32] * hk;
    }
    float m2 = wredsum(o0 + o1) * (1.0f / 64.0f);
    float c0 = o0 - m2, c1 = o1 - m2;
    float v2 = wredsum(c0 * c0 + c1 * c1) * (1.0f / 64.0f);
    float r  = rsqrtf(v2 + 1e-5f);
    float p0 = c0 * r * pe_g2[lane]      + pe_bn2[lane];
    float p1 = c1 * r * pe_g2[lane + 32] + pe_bn2[lane + 32];

    size_t base = (size_t)node * 256;
    store_split(g_xc_h, g_xc_l, base + 192 + lane, p0);
    store_split(g_xc_h, g_xc_l, base + 224 + lane, p1);
    #pragma unroll
    for (int i = lane; i < XDIM; i += 32)
        store_split(g_xc_h, g_xc_l, base + i, x[(size_t)node * XDIM + i]);
}

// ---------------- K2: bf16-split tensor-core GEMM core ---------------------
#define RS   40
#define MAT  (128 * RS)
#define STG  (4 * MAT)
#define GSMEM (2 * STG * 2)

__device__ __forceinline__ void tc_gemm_core(
        const __nv_bfloat16* __restrict__ Ah, const __nv_bfloat16* __restrict__ Al,
        const __nv_bfloat16* __restrict__ Wh, const __nv_bfloat16* __restrict__ Wl,
        const float* __restrict__ bias, float* __restrict__ C, int M,
        int m0, int f0, __nv_bfloat16* smem)
{
    uint32_t sbase = (uint32_t)__cvta_generic_to_shared(smem);

    int tid = threadIdx.x;
    int w = tid >> 5, l = tid & 31;
    int wm = w & 1, wn = w >> 1;

    int a_row = l & 15;
    int a_kof = (l >> 4) << 3;
    int b_row = (l & 7) + ((l >> 4) << 3);
    int b_kof = ((l >> 3) & 1) << 3;

    float acc[4][4][4];
    #pragma unroll
    for (int i = 0; i < 4; i++)
        #pragma unroll
        for (int j = 0; j < 4; j++)
            #pragma unroll
            for (int k = 0; k < 4; k++) acc[i][j][k] = 0.0f;

    auto load_stage = [&](int buf, int kt) {
        int kblk = kt * 32;
        #pragma unroll
        for (int i = 0; i < 2; i++) {
            int chunk = tid + i * 256;
            int row = chunk >> 2, sub = chunk & 3;
            uint32_t so = sbase + (uint32_t)(buf * STG + row * RS + sub * 8) * 2;
            cpa16(so,               Ah + (size_t)(m0 + row) * 256 + kblk + sub * 8);
            cpa16(so + MAT * 2,     Al + (size_t)(m0 + row) * 256 + kblk + sub * 8);
            cpa16(so + 2 * MAT * 2, Wh + (size_t)(f0 + row) * 256 + kblk + sub * 8);
            cpa16(so + 3 * MAT * 2, Wl + (size_t)(f0 + row) * 256 + kblk + sub * 8);
        }
    };

    load_stage(0, 0);
    asm volatile("cp.async.commit_group;");

    #pragma unroll 1
    for (int kt = 0; kt < 8; kt++) {
        if (kt < 7) {
            load_stage((kt + 1) & 1, kt + 1);
            asm volatile("cp.async.commit_group;");
            asm volatile("cp.async.wait_group 1;");
        } else {
            asm volatile("cp.async.wait_group 0;");
        }
        __syncthreads();

        int buf = kt & 1;
        uint32_t sA_h = sbase + (uint32_t)(buf * STG) * 2;
        uint32_t sA_l = sA_h + MAT * 2;
        uint32_t sW_h = sA_h + 2 * MAT * 2;
        uint32_t sW_l = sA_h + 3 * MAT * 2;

        #pragma unroll
        for (int kk = 0; kk < 32; kk += 16) {
            uint32_t bh[2][4], bl[2][4];
            #pragma unroll
            for (int g2 = 0; g2 < 2; g2++) {
                uint32_t boff = (uint32_t)((wn * 32 + g2 * 16 + b_row) * RS + kk + b_kof) * 2;
                ldm4(bh[g2], sW_h + boff);
                ldm4(bl[g2], sW_l + boff);
            }
            #pragma unroll
            for (int mt = 0; mt < 4; mt++) {
                uint32_t aoff = (uint32_t)((wm * 64 + mt * 16 + a_row) * RS + kk + a_kof) * 2;
                uint32_t ah[4], al[4];
                ldm4(ah, sA_h + aoff);
                ldm4(al, sA_l + aoff);
                #pragma unroll
                for (int nt = 0; nt < 4; nt++) {
                    const uint32_t* BH = &bh[nt >> 1][(nt & 1) * 2];
                    const uint32_t* BL = &bl[nt >> 1][(nt & 1) * 2];
                    mma_bf16(acc[mt][nt], ah, BH);
                    mma_bf16(acc[mt][nt], ah, BL);
                    mma_bf16(acc[mt][nt], al, BH);
                }
            }
        }
        __syncthreads();
    }

    #pragma unroll
    for (int mt = 0; mt < 4; mt++) {
        #pragma unroll
        for (int nt = 0; nt < 4; nt++) {
            int row0 = m0 + wm * 64 + mt * 16 + (l >> 2);
            int col  = f0 + wn * 32 + nt * 8 + (l & 3) * 2;
            float b0v = bias[col], b1v = bias[col + 1];
            if (row0 < M) {
                float2 v = make_float2(acc[mt][nt][0] + b0v, acc[mt][nt][1] + b1v);
                *(float2*)&C[(size_t)row0 * 256 + col] = v;
            }
            if (row0 + 8 < M) {
                float2 v = make_float2(acc[mt][nt][2] + b0v, acc[mt][nt][3] + b1v);
                *(float2*)&C[(size_t)(row0 + 8) * 256 + col] = v;
            }
        }
    }
}

__global__ __launch_bounds__(256) void tc_gemm3(
        const __nv_bfloat16* __restrict__ Ah, const __nv_bfloat16* __restrict__ Al,
        const float* __restrict__ b0, const float* __restrict__ b1,
        const float* __restrict__ b2,
        float* __restrict__ C0, float* __restrict__ C1, float* __restrict__ C2,
        int M)
{
    extern __shared__ __align__(16) __nv_bfloat16 smem[];
    int mi = blockIdx.y >> 1;
    int f0 = (blockIdx.y & 1) * 128;
    const float* bias = (mi == 0) ? b0 : (mi == 1) ? b1 : b2;
    float* C = (mi == 0) ? C0 : (mi == 1) ? C1 : C2;
    tc_gemm_core(Ah, Al, g_wh + (size_t)mi * 65536, g_wl + (size_t)mi * 65536,
                 bias, C, M, blockIdx.x * 128, f0, smem);
}

__global__ __launch_bounds__(256) void tc_gemm1(
        const __nv_bfloat16* __restrict__ Ah, const __nv_bfloat16* __restrict__ Al,
        const float* __restrict__ bias, float* __restrict__ C, int M)
{
    extern __shared__ __align__(16) __nv_bfloat16 smem[];
    tc_gemm_core(Ah, Al, g_wh + 3 * 65536, g_wl + 3 * 65536,
                 bias, C, M, blockIdx.x * 128, blockIdx.y * 128, smem);
}

// ---------------- K3: CSR build ----------------
__global__ void count_deg(const int* __restrict__ ei, int E) {
    int i = blockIdx.x * blockDim.x + threadIdx.x;
    if (i < E) atomicAdd(&g_deg[ei[E + i]], 1);
}

__global__ void scan_offsets(int n) {
    __shared__ int wsum[32];
    __shared__ int carry;
    int t = threadIdx.x, lane = t & 31, w = t >> 5;
    if (t == 0) { carry = 0; g_off[0] = 0; }
    __syncthreads();
    for (int base = 0; base < n; base += 1024) {
        int i = base + t;
        int v = (i < n) ? g_deg[i] : 0;
        int sc = v;
        #pragma unroll
        for (int s = 1; s < 32; s <<= 1) {
            int xv = __shfl_up_sync(0xffffffffu, sc, s);
            if (lane >= s) sc += xv;
        }
        if (lane == 31) wsum[w] = sc;
        __syncthreads();
        if (w == 0) {
            int ws = wsum[lane];
            #pragma unroll
            for (int s = 1; s < 32; s <<= 1) {
                int xv = __shfl_up_sync(0xffffffffu, ws, s);
                if (lane >= s) ws += xv;
            }
            wsum[lane] = ws;
        }
        __syncthreads();
        int add = carry + (w ? wsum[w - 1] : 0);
        if (i < n) g_off[i + 1] = add + sc;
        int total = wsum[31];
        __syncthreads();
        if (t == 0) carry += total;
        __syncthreads();
    }
}

__global__ void fill_csr(const int* __restrict__ ei, int E) {
    int i = blockIdx.x * blockDim.x + threadIdx.x;
    if (i < E) {
        int d = ei[E + i];
        int p = g_off[d] + atomicAdd(&g_fill[d], 1);
        g_ceid[p] = i;
        g_csrc[p] = ei[i];
    }
}

// ---------------- K4: FUSED per-node kernel (128 threads) ------------------
__global__ __launch_bounds__(128) void fused_node(
        const float* __restrict__ lin_e_w, const float* __restrict__ att,
        const float* __restrict__ conv_b, const float* __restrict__ norm_g,
        const float* __restrict__ norm_b, float* __restrict__ dout,
        size_t AL_OFF, size_t EA_OFF, int n)
{
    __shared__ __align__(16) float s_xr[256];
    __shared__ __align__(16) float s_ew[768];
    __shared__ __align__(16) float s_att[256];
    __shared__ int   s_src[DEGC];
    __shared__ int   s_eid[DEGC];
    __shared__ __align__(16) float s_logit[DEGC * 4];
    __shared__ __align__(16) float s_acc[2][256];
    __shared__ float sh_red[16], sh_m[4], sh_inv[4];
    __shared__ float shs[4], shq[4];
    __shared__ float sh_mean, sh_rstd, s_nud0, s_nud1;

    int node = blockIdx.x;
    int t = threadIdx.x;
    int lane = t & 31, warp = t >> 5;
    int start = g_off[node];
    int deg   = g_off[node + 1] - start;

    for (int i = t; i < 256; i += 128) { s_xr[i] = g_xr[(size_t)node * 256 + i]; s_att[i] = att[i]; }
    for (int i = t; i < 768; i += 128)
        s_ew[(i % 3) * 256 + (i / 3)] = lin_e_w[i];
    if (t == 0) { s_nud0 = g_nu[2 * node]; s_nud1 = g_nu[2 * node + 1]; }
    __syncthreads();

    bool small = (deg <= DEGC);

    // ---- pass 1: logits, warp per edge, paired loads for MLP ----
    for (int c0 = 0; c0 < deg; c0 += DEGC) {
        int cnt = min(DEGC, deg - c0);
        for (int j = t; j < cnt; j += 128) {
            s_src[j] = g_csrc[start + c0 + j];
            s_eid[j] = g_ceid[start + c0 + j];
        }
        __syncthreads();
        for (int j = warp; j < cnt; j += 8) {
            int jB = j + 4;
            bool two = (jB < cnt);
            int sA = s_src[j];
            int sB = two ? s_src[jB] : sA;
            // issue all global loads up front (2 nu pairs + 4x LDG.128)
            float nuA0 = __ldg(&g_nu[2 * sA]), nuA1 = __ldg(&g_nu[2 * sA + 1]);
            float nuB0 = __ldg(&g_nu[2 * sB]), nuB1 = __ldg(&g_nu[2 * sB + 1]);
            int f0 = lane * 8;
            const float* xA = &g_xl[(size_t)sA * 256 + f0];
            const float* xB = &g_xl[(size_t)sB * 256 + f0];
            float4 lA0 = *(const float4*)xA, lA1 = *(const float4*)(xA + 4);
            float4 lB0 = *(const float4*)xB, lB1 = *(const float4*)(xB + 4);

            float4 r0 = *(const float4*)&s_xr[f0],        r1 = *(const float4*)&s_xr[f0 + 4];
            float4 e00 = *(const float4*)&s_ew[f0],       e01 = *(const float4*)&s_ew[f0 + 4];
            float4 e10 = *(const float4*)&s_ew[256 + f0], e11 = *(const float4*)&s_ew[256 + f0 + 4];
            float4 e20 = *(const float4*)&s_ew[512 + f0], e21 = *(const float4*)&s_ew[512 + f0 + 4];
            float4 at0 = *(const float4*)&s_att[f0],      at1 = *(const float4*)&s_att[f0 + 4];
            float rr[8]  = {r0.x, r0.y, r0.z, r0.w, r1.x, r1.y, r1.z, r1.w};
            float e0a[8] = {e00.x, e00.y, e00.z, e00.w, e01.x, e01.y, e01.z, e01.w};
            float e1a[8] = {e10.x, e10.y, e10.z, e10.w, e11.x, e11.y, e11.z, e11.w};
            float e2a[8] = {e20.x, e20.y, e20.z, e20.w, e21.x, e21.y, e21.z, e21.w};
            float ata[8] = {at0.x, at0.y, at0.z, at0.w, at1.x, at1.y, at1.z, at1.w};

            // edge A
            {
                float a0 = s_nud0 - nuA0, a1 = s_nud1 - nuA1;
                float a2 = sqrtf(a0 * a0 + a1 * a1);
                int eid = s_eid[j];
                if (lane == 0) {
                    dout[EA_OFF + (size_t)eid * 3]     = a0;
                    dout[EA_OFF + (size_t)eid * 3 + 1] = a1;
                    dout[EA_OFF + (size_t)eid * 3 + 2] = a2;
                }
                float xs[8] = {lA0.x, lA0.y, lA0.z, lA0.w, lA1.x, lA1.y, lA1.z, lA1.w};
                float acc = 0.0f;
                #pragma unroll
                for (int i = 0; i < 8; i++) {
                    float vv = xs[i] + rr[i] + e0a[i] * a0 + e1a[i] * a1 + e2a[i] * a2;
                    vv = vv > 0.0f ? vv : 0.2f * vv;
                    acc += vv * ata[i];
                }
                acc += __shfl_xor_sync(0xffffffffu, acc, 1);
                acc += __shfl_xor_sync(0xffffffffu, acc, 2);
                acc += __shfl_xor_sync(0xffffffffu, acc, 4);
                if ((lane & 7) == 0) {
                    if (small) s_logit[j * 4 + (lane >> 3)] = acc;
                    else       g_logits[(size_t)eid * 4 + (lane >> 3)] = acc;
                }
            }
            // edge B
            if (two) {
                float a0 = s_nud0 - nuB0, a1 = s_nud1 - nuB1;
                float a2 = sqrtf(a0 * a0 + a1 * a1);
                int eid = s_eid[jB];
                if (lane == 0) {
                    dout[EA_OFF + (size_t)eid * 3]     = a0;
                    dout[EA_OFF + (size_t)eid * 3 + 1] = a1;
                    dout[EA_OFF + (size_t)eid * 3 + 2] = a2;
                }
                float xs[8] = {lB0.x, lB0.y, lB0.z, lB0.w, lB1.x, lB1.y, lB1.z, lB1.w};
                float acc = 0.0f;
                #pragma unroll
                for (int i = 0; i < 8; i++) {
                    float vv = xs[i] + rr[i] + e0a[i] * a0 + e1a[i] * a1 + e2a[i] * a2;
                    vv = vv > 0.0f ? vv : 0.2f * vv;
                    acc += vv * ata[i];
                }
                acc += __shfl_xor_sync(0xffffffffu, acc, 1);
                acc += __shfl_xor_sync(0xffffffffu, acc, 2);
                acc += __shfl_xor_sync(0xffffffffu, acc, 4);
                if ((lane & 7) == 0) {
                    if (small) s_logit[jB * 4 + (lane >> 3)] = acc;
                    else       g_logits[(size_t)eid * 4 + (lane >> 3)] = acc;
                }
            }
        }
        __syncthreads();
    }

    // ---- softmax over destination neighborhood (128 threads) ----
    int h = t & 3;
    float mx = -1e30f;
    if (small) {
        for (int j = t >> 2; j < deg; j += 32)
            mx = fmaxf(mx, s_logit[j * 4 + h]);
    } else {
        for (int j = t >> 2; j < deg; j += 32) {
            int eid = g_ceid[start + j];
            mx = fmaxf(mx, g_logits[(size_t)eid * 4 + h]);
        }
    }
    mx = fmaxf(mx, __shfl_xor_sync(0xffffffffu, mx, 4));
    mx = fmaxf(mx, __shfl_xor_sync(0xffffffffu, mx, 8));
    mx = fmaxf(mx, __shfl_xor_sync(0xffffffffu, mx, 16));
    if (lane < 4) sh_red[warp * 4 + lane] = mx;
    __syncthreads();
    if (t < 4) {
        float m = sh_red[t];
        #pragma unroll
        for (int wq = 1; wq < 4; wq++) m = fmaxf(m, sh_red[wq * 4 + t]);
        sh_m[t] = m;
    }
    __syncthreads();

    float mh = sh_m[h];
    float sm = 0.0f;
    if (small) {
        for (int j = t >> 2; j < deg; j += 32) {
            float e = expf(s_logit[j * 4 + h] - mh);
            s_logit[j * 4 + h] = e;
            sm += e;
        }
    } else {
        for (int j = t >> 2; j < deg; j += 32) {
            int eid = g_ceid[start + j];
            float e = expf(g_logits[(size_t)eid * 4 + h] - mh);
            g_logits[(size_t)eid * 4 + h] = e;
            sm += e;
        }
    }
    sm += __shfl_xor_sync(0xffffffffu, sm, 4);
    sm += __shfl_xor_sync(0xffffffffu, sm, 8);
    sm += __shfl_xor_sync(0xffffffffu, sm, 16);
    if (lane < 4) sh_red[warp * 4 + lane] = sm;
    __syncthreads();
    if (t < 4) {
        float s = 0.0f;
        #pragma unroll
        for (int wq = 0; wq < 4; wq++) s += sh_red[wq * 4 + t];
        sh_inv[t] = 1.0f / (s + 1e-16f);
    }
    __syncthreads();

    float invh = sh_inv[h];
    if (small) {
        for (int j = t >> 2; j < deg; j += 32) {
            float al = s_logit[j * 4 + h] * invh;
            s_logit[j * 4 + h] = al;
            dout[AL_OFF + (size_t)s_eid[j] * 4 + h] = al;
        }
    } else {
        for (int j = t >> 2; j < deg; j += 32) {
            int eid = g_ceid[start + j];
            float al = g_logits[(size_t)eid * 4 + h] * invh;
            g_logits[(size_t)eid * 4 + h] = al;
            dout[AL_OFF + (size_t)eid * 4 + h] = al;
        }
    }
    __syncthreads();

    // ---- weighted gather-accumulate: 64 threads x float4 per row,
    //      two edge-groups in parallel ----
    int grp = t >> 6, ft = t & 63;
    int hq = ft >> 4;                      // head of features 4ft..4ft+3
    float4 a4 = make_float4(0.f, 0.f, 0.f, 0.f);
    if (small) {
        int j = grp;
        for (; j + 2 < deg; j += 4) {
            int sa = s_src[j], sb = s_src[j + 2];
            float ala = s_logit[j * 4 + hq], alb = s_logit[(j + 2) * 4 + hq];
            float4 xa = *(const float4*)&g_xl[(size_t)sa * 256 + 4 * ft];
            float4 xb = *(const float4*)&g_xl[(size_t)sb * 256 + 4 * ft];
            a4.x += ala * xa.x + alb * xb.x;
            a4.y += ala * xa.y + alb * xb.y;
            a4.z += ala * xa.z + alb * xb.z;
            a4.w += ala * xa.w + alb * xb.w;
        }
        for (; j < deg; j += 2) {
            int sa = s_src[j];
            float ala = s_logit[j * 4 + hq];
            float4 xa = *(const float4*)&g_xl[(size_t)sa * 256 + 4 * ft];
            a4.x += ala * xa.x; a4.y += ala * xa.y;
            a4.z += ala * xa.z; a4.w += ala * xa.w;
        }
    } else {
        for (int c0 = 0; c0 < deg; c0 += DEGC) {
            int cnt = min(DEGC, deg - c0);
            for (int j = t; j < cnt; j += 128)
                s_src[j] = g_csrc[start + c0 + j];
            for (int i = t; i < cnt * 4; i += 128)
                s_logit[i] = g_logits[(size_t)g_ceid[start + c0 + (i >> 2)] * 4 + (i & 3)];
            __syncthreads();
            int j = grp;
            for (; j + 2 < cnt; j += 4) {
                int sa = s_src[j], sb = s_src[j + 2];
                float ala = s_logit[j * 4 + hq], alb = s_logit[(j + 2) * 4 + hq];
                float4 xa = *(const float4*)&g_xl[(size_t)sa * 256 + 4 * ft];
                float4 xb = *(const float4*)&g_xl[(size_t)sb * 256 + 4 * ft];
                a4.x += ala * xa.x + alb * xb.x;
                a4.y += ala * xa.y + alb * xb.y;
                a4.z += ala * xa.z + alb * xb.z;
                a4.w += ala * xa.w + alb * xb.w;
            }
            for (; j < cnt; j += 2) {
                int sa = s_src[j];
                float ala = s_logit[j * 4 + hq];
                float4 xa = *(const float4*)&g_xl[(size_t)sa * 256 + 4 * ft];
                a4.x += ala * xa.x; a4.y += ala * xa.y;
                a4.z += ala * xa.z; a4.w += ala * xa.w;
            }
            __syncthreads();
        }
    }
    *(float4*)&s_acc[grp][4 * ft] = a4;
    __syncthreads();

    // ---- epilogue: +conv_b, LN(256), +identity, silu; 2 features / thread ----
    int f0e = 2 * t;
    float v0 = s_acc[0][f0e]     + s_acc[1][f0e]     + conv_b[f0e];
    float v1 = s_acc[0][f0e + 1] + s_acc[1][f0e + 1] + conv_b[f0e + 1];
    float sv = v0 + v1, sq = v0 * v0 + v1 * v1;
    #pragma unroll
    for (int ss = 16; ss; ss >>= 1) {
        sv += __shfl_xor_sync(0xffffffffu, sv, ss);
        sq += __shfl_xor_sync(0xffffffffu, sq, ss);
    }
    if (lane == 0) { shs[warp] = sv; shq[warp] = sq; }
    __syncthreads();
    if (t == 0) {
        float a = shs[0] + shs[1] + shs[2] + shs[3];
        float b = shq[0] + shq[1] + shq[2] + shq[3];
        float mean = a * (1.0f / 256.0f);
        float var  = b * (1.0f / 256.0f) - mean * mean;
        sh_mean = mean;
        sh_rstd = rsqrtf(var + 1e-5f);
    }
    __syncthreads();
    float y0 = (v0 - sh_mean) * sh_rstd * norm_g[f0e]     + norm_b[f0e];
    float y1 = (v1 - sh_mean) * sh_rstd * norm_g[f0e + 1] + norm_b[f0e + 1];
    float z0 = y0 + g_iden[(size_t)node * 256 + f0e];
    float z1 = y1 + g_iden[(size_t)node * 256 + f0e + 1];
    store_split(g_act_h, g_act_l, (size_t)node * 256 + f0e,     z0 / (1.0f + expf(-z0)));
    store_split(g_act_h, g_act_l, (size_t)node * 256 + f0e + 1, z1 / (1.0f + expf(-z1)));
}

// ---------------- host ----------------
extern "C" void kernel_launch(void* const* d_in, const int* in_sizes, int n_in,
                              void* d_out, int out_size)
{
    const float* x        = (const float*)d_in[0];
    const float* kpts     = (const float*)d_in[1];
    const float* pts3     = (const float*)d_in[2];
    const float* pe_w1    = (const float*)d_in[3];
    const float* pe_b1    = (const float*)d_in[4];
    const float* pe_g1    = (const float*)d_in[5];
    const float* pe_bn1   = (const float*)d_in[6];
    const float* pe_w2    = (const float*)d_in[7];
    const float* pe_b2    = (const float*)d_in[8];
    const float* pe_g2    = (const float*)d_in[9];
    const float* pe_bn2   = (const float*)d_in[10];
    const float* lin_l_w  = (const float*)d_in[11];
    const float* lin_l_b  = (const float*)d_in[12];
    const float* lin_r_w  = (const float*)d_in[13];
    const float* lin_r_b  = (const float*)d_in[14];
    const float* lin_e_w  = (const float*)d_in[15];
    const float* att      = (const float*)d_in[16];
    const float* conv_b   = (const float*)d_in[17];
    const float* norm_g   = (const float*)d_in[18];
    const float* norm_b   = (const float*)d_in[19];
    const float* res_w    = (const float*)d_in[20];
    const float* res_b    = (const float*)d_in[21];
    const float* proj_w   = (const float*)d_in[22];
    const float* proj_b   = (const float*)d_in[23];
    const int*   ei       = (const int*)d_in[24];

    int n = in_sizes[0] / XDIM;          // 50000
    int E = in_sizes[24] / 2;            // 800000
    float* out = (float*)d_out;
    size_t AL_OFF = (size_t)n * 256;
    size_t EA_OFF = AL_OFF + (size_t)E * 4;

    void *p_xch, *p_xcl, *p_acth, *p_actl, *p_xl, *p_xr, *p_iden;
    cudaGetSymbolAddress(&p_xch,  g_xc_h);
    cudaGetSymbolAddress(&p_xcl,  g_xc_l);
    cudaGetSymbolAddress(&p_acth, g_act_h);
    cudaGetSymbolAddress(&p_actl, g_act_l);
    cudaGetSymbolAddress(&p_xl,   g_xl);
    cudaGetSymbolAddress(&p_xr,   g_xr);
    cudaGetSymbolAddress(&p_iden, g_iden);

    cudaFuncSetAttribute(tc_gemm3, cudaFuncAttributeMaxDynamicSharedMemorySize, GSMEM);
    cudaFuncSetAttribute(tc_gemm1, cudaFuncAttributeMaxDynamicSharedMemorySize, GSMEM);

    // 0) zero counters + weight conversion
    zero_counts<<<(n + 256) / 256, 256>>>(n);
    conv_w<<<dim3(256, 4), 256>>>(lin_l_w, lin_r_w, res_w, proj_w);

    // 1) positional encoder + concat (writes xcomb hi/lo)
    node_pre<<<(n * 32 + 255) / 256, 256>>>(x, kpts, pts3,
                                            pe_w1, pe_b1, pe_g1, pe_bn1,
                                            pe_w2, pe_b2, pe_g2, pe_bn2, n);

    // 2) dense transforms on tensor cores (3 GEMMs merged)
    dim3 gg3((n + 127) / 128, 6);
    tc_gemm3<<<gg3, 256, GSMEM>>>((const __nv_bfloat16*)p_xch, (const __nv_bfloat16*)p_xcl,
                                  lin_l_b, lin_r_b, res_b,
                                  (float*)p_xl, (float*)p_xr, (float*)p_iden, n);

    // 3) CSR by destination
    count_deg<<<(E + 255) / 256, 256>>>(ei, E);
    scan_offsets<<<1, 1024>>>(n);
    fill_csr<<<(E + 255) / 256, 256>>>(ei, E);

    // 4) fused: edge attrs + logits + softmax + aggregate + epilogue
    fused_node<<<n, 128>>>(lin_e_w, att, conv_b, norm_g, norm_b,
                           out, AL_OFF, EA_OFF, n);

    // 5) final projection -> out
    dim3 gg1((n + 127) / 128, 2);
    tc_gemm1<<<gg1, 256, GSMEM>>>((const __nv_bfloat16*)p_acth, (const __nv_bfloat16*)p_actl,
                                  proj_b, out, n);
}